// round 9
// baseline (speedup 1.0000x reference)
#include <cuda_runtime.h>
#include <cuda_fp16.h>
#include <cstdint>

#define D_MODEL 2048
#define KV_DIM  512
#define NHEADS  32
#define NKVH    8
#define HD      64
#define SEQ     1024
#define BATCH   4
#define MTOT    (BATCH * SEQ)   // 4096
#define NQKV    (D_MODEL + 2 * KV_DIM)  // 3072

// ---------------- scratch (no cudaMalloc allowed) ----------------
__device__ __align__(256) __half g_qh[MTOT * D_MODEL];
__device__ __align__(256) __half g_kh[MTOT * KV_DIM];
__device__ __align__(256) __half g_vh[MTOT * KV_DIM];
__device__ __align__(256) __half g_vt[MTOT * KV_DIM];      // V transposed [b][kvh][d][seq]
__device__ __align__(256) __half g_ch[MTOT * D_MODEL];     // attention ctx (fp16)
__device__ __align__(256) __half g_xh[MTOT * D_MODEL];     // x in fp16
__device__ __align__(256) __half g_wt3[NQKV * D_MODEL];    // [Wq;Wk;Wv] transposed fp16
__device__ __align__(256) __half g_wto[D_MODEL * D_MODEL]; // Wo transposed fp16

// ================= helpers =================
__device__ __forceinline__ uint32_t smem_u32(const void* p) {
    uint32_t a;
    asm("{ .reg .u64 t; cvta.to.shared.u64 t, %1; cvt.u32.u64 %0, t; }" : "=r"(a) : "l"(p));
    return a;
}
__device__ __forceinline__ void mma_f16(float c[4], uint32_t a0, uint32_t a1,
                                        uint32_t a2, uint32_t a3,
                                        uint32_t b0, uint32_t b1) {
    asm volatile(
        "mma.sync.aligned.m16n8k16.row.col.f32.f16.f16.f32 "
        "{%0,%1,%2,%3}, {%4,%5,%6,%7}, {%8,%9}, {%0,%1,%2,%3};"
        : "+f"(c[0]), "+f"(c[1]), "+f"(c[2]), "+f"(c[3])
        : "r"(a0), "r"(a1), "r"(a2), "r"(a3), "r"(b0), "r"(b1));
}
__device__ __forceinline__ void ldm_x4(uint32_t& r0, uint32_t& r1,
                                       uint32_t& r2, uint32_t& r3, uint32_t addr) {
    asm volatile("ldmatrix.sync.aligned.m8n8.x4.shared.b16 {%0,%1,%2,%3}, [%4];"
                 : "=r"(r0), "=r"(r1), "=r"(r2), "=r"(r3) : "r"(addr));
}

// ================= prep kernels =================
__global__ void to_half_kernel(const float4* __restrict__ in, uint2* __restrict__ out, int n4) {
    int i = blockIdx.x * blockDim.x + threadIdx.x;
    if (i < n4) {
        float4 v = in[i];
        __half2 h0 = __floats2half2_rn(v.x, v.y);
        __half2 h1 = __floats2half2_rn(v.z, v.w);
        out[i] = make_uint2(*(uint32_t*)&h0, *(uint32_t*)&h1);
    }
}

// W [K, N] fp32 row-major -> Wt [N, K] fp16 row-major
__global__ void transpose_half_kernel(const float* __restrict__ W, __half* __restrict__ Wt,
                                      int K, int N) {
    __shared__ float t[32][33];
    const int n0 = blockIdx.x * 32, k0 = blockIdx.y * 32;
    const int tx = threadIdx.x, ty = threadIdx.y;  // 32 x 8
    #pragma unroll
    for (int i = 0; i < 32; i += 8)
        t[ty + i][tx] = W[(size_t)(k0 + ty + i) * N + n0 + tx];
    __syncthreads();
    #pragma unroll
    for (int i = 0; i < 32; i += 8)
        Wt[(size_t)(n0 + ty + i) * K + k0 + tx] = __float2half_rn(t[tx][ty + i]);
}

// v [MTOT][KV_DIM] fp16 -> vt [(b*KV_DIM + c)][SEQ] fp16
__global__ void vtrans_kernel(const __half* __restrict__ v, __half* __restrict__ vt) {
    __shared__ __half t[32][34];
    const int s0 = blockIdx.x * 32, c0 = blockIdx.y * 32, b = blockIdx.z;
    const int tx = threadIdx.x, ty = threadIdx.y;  // 32 x 8
    #pragma unroll
    for (int i = 0; i < 32; i += 8)
        t[ty + i][tx] = v[(size_t)(b * SEQ + s0 + ty + i) * KV_DIM + c0 + tx];
    __syncthreads();
    #pragma unroll
    for (int i = 0; i < 32; i += 8)
        vt[(size_t)(b * KV_DIM + c0 + ty + i) * SEQ + s0 + tx] = t[tx][ty + i];
}

// ================= fp16 warp-MMA GEMM (ldmatrix, 2-stage, 2 CTA/SM) =======
// 128x128 tile, BK=64 halfs, 8 warps (2x4 -> 64x32 each). Pitch 72 halfs.
// mode 1: fused QKV — route output block to q/k/v fp16 buffers by column.
// mode 0: fp32 output + single bias.
#define GPH  72
#define GA_STAGE (128 * GPH)            // halfs
#define GSTAGE_H (2 * 128 * GPH)
#define GEMM_SMEM (2 * GSTAGE_H * 2)    // 73728 B

__global__ __launch_bounds__(256, 2) void gemm_h_kernel(
    const __half* __restrict__ A, const __half* __restrict__ Bt,
    const float* __restrict__ bias0, const float* __restrict__ bias1,
    const float* __restrict__ bias2,
    float* __restrict__ outF,
    __half* __restrict__ outQ, __half* __restrict__ outK, __half* __restrict__ outV,
    int M, int N, int K, int mode)
{
    extern __shared__ __align__(16) __half hsm[];

    const int tid  = threadIdx.x;
    const int wid  = tid >> 5;
    const int lane = tid & 31;
    const int m0 = blockIdx.y * 128;
    const int n0 = blockIdx.x * 128;
    const int wm = wid & 1;
    const int wn = wid >> 1;
    const int frow = lane >> 2;
    const int t4   = lane & 3;

    const bool isA = tid < 128;
    const int  row = isA ? tid : tid - 128;
    const __half* gsrc = isA ? (A + (size_t)(m0 + row) * K)
                             : (Bt + (size_t)(n0 + row) * K);
    const uint32_t smem_base = smem_u32(hsm);
    const uint32_t sdst_row = smem_base + ((isA ? 0 : GA_STAGE) + row * GPH) * 2;

    // ldmatrix lane offsets (bytes, relative to stage base)
    uint32_t aOff[4];
    #pragma unroll
    for (int mi = 0; mi < 4; mi++)
        aOff[mi] = ((wm * 64 + mi * 16 + (lane & 15)) * GPH + (lane >> 4) * 8) * 2;
    const uint32_t bOff = ((wn * 32 + (lane >> 3) * 8 + (lane & 7)) * GPH) * 2;

    const int nChunks = K / 64;

    #define GISSUE(ch, st) do {                                                \
        uint32_t _d = sdst_row + (st) * (GSTAGE_H * 2);                        \
        const __half* _g = gsrc + (ch) * 64;                                   \
        _Pragma("unroll")                                                      \
        for (int _c = 0; _c < 8; _c++)                                         \
            asm volatile("cp.async.cg.shared.global [%0], [%1], 16;"           \
                         :: "r"(_d + _c * 16), "l"(_g + _c * 8) : "memory");   \
    } while (0)

    GISSUE(0, 0);
    asm volatile("cp.async.commit_group;" ::: "memory");

    float acc[4][4][4];
    #pragma unroll
    for (int mi = 0; mi < 4; mi++)
        #pragma unroll
        for (int ni = 0; ni < 4; ni++)
            #pragma unroll
            for (int r = 0; r < 4; r++) acc[mi][ni][r] = 0.f;

    for (int ch = 0; ch < nChunks; ch++) {
        __syncthreads();   // everyone done reading the buffer we're about to fill
        if (ch + 1 < nChunks) GISSUE(ch + 1, (ch + 1) & 1);
        asm volatile("cp.async.commit_group;" ::: "memory");
        asm volatile("cp.async.wait_group 1;" ::: "memory");
        __syncthreads();   // chunk ch visible to all

        const uint32_t stA = smem_base + (ch & 1) * (GSTAGE_H * 2);
        const uint32_t stB = stA + GA_STAGE * 2;

        #pragma unroll
        for (int ks = 0; ks < 4; ks++) {
            const uint32_t kb = ks * 32;   // bytes
            uint32_t a[4][4], b0[4], b1[4];
            #pragma unroll
            for (int mi = 0; mi < 4; mi++)
                ldm_x4(a[mi][0], a[mi][1], a[mi][2], a[mi][3], stA + aOff[mi] + kb);
            ldm_x4(b0[0], b0[1], b0[2], b0[3], stB + bOff + kb);
            ldm_x4(b1[0], b1[1], b1[2], b1[3], stB + bOff + kb + 16);
            #pragma unroll
            for (int mi = 0; mi < 4; mi++)
                #pragma unroll
                for (int ni = 0; ni < 4; ni++)
                    mma_f16(acc[mi][ni], a[mi][0], a[mi][1], a[mi][2], a[mi][3],
                            b0[ni], b1[ni]);
        }
    }
    #undef GISSUE

    // ---- epilogue ----
    const float* bias = bias0;
    __half* dstH = outQ;
    int colbase = n0, stride = N;
    if (mode == 1) {
        if (n0 < D_MODEL)               { dstH = outQ; bias = bias0; colbase = n0;              stride = D_MODEL; }
        else if (n0 < D_MODEL + KV_DIM) { dstH = outK; bias = bias1; colbase = n0 - D_MODEL;    stride = KV_DIM; }
        else                            { dstH = outV; bias = bias2; colbase = n0 - D_MODEL - KV_DIM; stride = KV_DIM; }
    }

    #pragma unroll
    for (int mi = 0; mi < 4; mi++) {
        const int r0 = m0 + wm * 64 + mi * 16 + frow;
        #pragma unroll
        for (int ni = 0; ni < 4; ni++) {
            const int col = colbase + wn * 32 + ni * 8 + 2 * t4;
            const float b0 = bias[col], b1 = bias[col + 1];
            const float v00 = acc[mi][ni][0] + b0, v01 = acc[mi][ni][1] + b1;
            const float v10 = acc[mi][ni][2] + b0, v11 = acc[mi][ni][3] + b1;
            if (mode == 1) {
                *(__half2*)(dstH + (size_t)r0 * stride + col) = __floats2half2_rn(v00, v01);
                *(__half2*)(dstH + (size_t)(r0 + 8) * stride + col) = __floats2half2_rn(v10, v11);
            } else {
                *(float2*)(outF + (size_t)r0 * stride + col) = make_float2(v00, v01);
                *(float2*)(outF + (size_t)(r0 + 8) * stride + col) = make_float2(v10, v11);
            }
        }
    }
}

// =================================================================
// fp16 tensor-core flash attention, ldmatrix + double-buffered K/V.
// =================================================================
#define AQ 72      // Q/K pitch (halfs): 144 B
#define AV 136     // Vt/P pitch (halfs): 272 B
#define KT_HALFS (128 * AQ)
#define VT_HALFS (64 * AV)
#define SQ 0
#define SK0 (SQ + 128 * AQ)
#define SV0 (SK0 + 2 * KT_HALFS)
#define SP  (SV0 + 2 * VT_HALFS)
#define ATTN_HALFS (SP + 128 * AV)
#define ATTN_SMEM_BYTES (ATTN_HALFS * 2)   // 124928 B

__global__ __launch_bounds__(256, 1) void attn_h_kernel(
    const __half* __restrict__ q, const __half* __restrict__ k,
    const __half* __restrict__ vt, __half* __restrict__ ctx)
{
    extern __shared__ __align__(16) __half hsm[];

    const int tid  = threadIdx.x;
    const int wid  = tid >> 5;
    const int lane = tid & 31;
    const int frow = lane >> 2;
    const int t4   = lane & 3;
    const int qt = blockIdx.x;
    const int h  = blockIdx.y;
    const int b  = blockIdx.z;
    const int kvh = h >> 2;

    const int qrow0 = b * SEQ + qt * 128;
    const __half* qbase = q + (size_t)qrow0 * D_MODEL + h * HD;
    const __half* kbase = k + (size_t)b * SEQ * KV_DIM + kvh * HD;
    const __half* vtbase = vt + (size_t)(b * KV_DIM + kvh * HD) * SEQ;

    const uint32_t smb = smem_u32(hsm);
    const int srow = tid >> 1;
    const int sc   = (tid & 1) * 32;
    const int vrow = tid >> 2;
    const int vc   = (tid & 3) * 32;

    {
        const __half* g = qbase + (size_t)srow * D_MODEL + sc;
        uint32_t d = smb + (SQ + srow * AQ + sc) * 2;
        #pragma unroll
        for (int c = 0; c < 4; c++)
            asm volatile("cp.async.cg.shared.global [%0], [%1], 16;"
                         :: "r"(d + c * 16), "l"(g + c * 8) : "memory");
        asm volatile("cp.async.commit_group;" ::: "memory");
    }

    #define STAGE_KV(kt, buf) do {                                             \
        const __half* gk = kbase + (size_t)((kt) * 128 + srow) * KV_DIM + sc;  \
        uint32_t dk = smb + (SK0 + (buf) * KT_HALFS + srow * AQ + sc) * 2;     \
        _Pragma("unroll")                                                      \
        for (int c = 0; c < 4; c++)                                            \
            asm volatile("cp.async.cg.shared.global [%0], [%1], 16;"           \
                         :: "r"(dk + c * 16), "l"(gk + c * 8) : "memory");     \
        const __half* gv = vtbase + (size_t)vrow * SEQ + (kt) * 128 + vc;      \
        uint32_t dv = smb + (SV0 + (buf) * VT_HALFS + vrow * AV + vc) * 2;     \
        _Pragma("unroll")                                                      \
        for (int c = 0; c < 4; c++)                                            \
            asm volatile("cp.async.cg.shared.global [%0], [%1], 16;"           \
                         :: "r"(dv + c * 16), "l"(gv + c * 8) : "memory");     \
    } while (0)

    STAGE_KV(0, 0);
    asm volatile("cp.async.commit_group;" ::: "memory");

    const uint32_t qOff = ((wid * 16 + (lane & 15)) * AQ + (lane >> 4) * 8) * 2;
    const uint32_t pOff = ((wid * 16 + (lane & 15)) * AV + (lane >> 4) * 8) * 2;
    uint32_t kOff[4], vOff[2];
    #pragma unroll
    for (int gg = 0; gg < 4; gg++)
        kOff[gg] = (((4 * gg + (lane >> 3)) * 8 + (lane & 7)) * AQ) * 2;
    #pragma unroll
    for (int gg = 0; gg < 2; gg++)
        vOff[gg] = (((4 * gg + (lane >> 3)) * 8 + (lane & 7)) * AV) * 2;

    float mrow[2] = {-1e30f, -1e30f};
    float lrow[2] = {0.f, 0.f};
    float accO[8][4];
    #pragma unroll
    for (int ni = 0; ni < 8; ni++)
        #pragma unroll
        for (int r = 0; r < 4; r++) accO[ni][r] = 0.f;

    for (int kt = 0; kt < SEQ / 128; kt++) {
        __syncthreads();
        if (kt + 1 < SEQ / 128) STAGE_KV(kt + 1, (kt + 1) & 1);
        asm volatile("cp.async.commit_group;" ::: "memory");
        asm volatile("cp.async.wait_group 1;" ::: "memory");
        __syncthreads();

        const uint32_t kBase = smb + (SK0 + (kt & 1) * KT_HALFS) * 2;
        const uint32_t vBase = smb + (SV0 + (kt & 1) * VT_HALFS) * 2;
        const uint32_t qBase = smb + SQ * 2;
        const uint32_t pBase = smb + SP * 2;

        float accS[16][4];
        #pragma unroll
        for (int ni = 0; ni < 16; ni++)
            #pragma unroll
            for (int r = 0; r < 4; r++) accS[ni][r] = 0.f;

        #pragma unroll
        for (int ks = 0; ks < 4; ks++) {
            const uint32_t kb = ks * 32;
            uint32_t a0, a1, a2, a3;
            ldm_x4(a0, a1, a2, a3, qBase + qOff + kb);
            #pragma unroll
            for (int gg = 0; gg < 4; gg++) {
                uint32_t b0[4], b1[4];
                ldm_x4(b0[0], b0[1], b0[2], b0[3], kBase + kOff[gg] + kb);
                ldm_x4(b1[0], b1[1], b1[2], b1[3], kBase + kOff[gg] + kb + 16);
                #pragma unroll
                for (int j = 0; j < 4; j++)
                    mma_f16(accS[4 * gg + j], a0, a1, a2, a3, b0[j], b1[j]);
            }
        }

        float mx0 = -1e30f, mx1 = -1e30f;
        #pragma unroll
        for (int ni = 0; ni < 16; ni++) {
            #pragma unroll
            for (int r = 0; r < 4; r++) accS[ni][r] *= 0.125f;
            mx0 = fmaxf(mx0, fmaxf(accS[ni][0], accS[ni][1]));
            mx1 = fmaxf(mx1, fmaxf(accS[ni][2], accS[ni][3]));
        }
        mx0 = fmaxf(mx0, __shfl_xor_sync(0xffffffffu, mx0, 1));
        mx0 = fmaxf(mx0, __shfl_xor_sync(0xffffffffu, mx0, 2));
        mx1 = fmaxf(mx1, __shfl_xor_sync(0xffffffffu, mx1, 1));
        mx1 = fmaxf(mx1, __shfl_xor_sync(0xffffffffu, mx1, 2));

        const float mn0 = fmaxf(mrow[0], mx0);
        const float mn1 = fmaxf(mrow[1], mx1);
        const float corr0 = __expf(mrow[0] - mn0);
        const float corr1 = __expf(mrow[1] - mn1);
        mrow[0] = mn0; mrow[1] = mn1;

        __half* Pw = hsm + SP + (wid * 16) * AV;
        float sum0 = 0.f, sum1 = 0.f;
        #pragma unroll
        for (int ni = 0; ni < 16; ni++) {
            float p0 = __expf(accS[ni][0] - mn0);
            float p1 = __expf(accS[ni][1] - mn0);
            float p2 = __expf(accS[ni][2] - mn1);
            float p3 = __expf(accS[ni][3] - mn1);
            sum0 += p0 + p1;
            sum1 += p2 + p3;
            const int col = ni * 8 + 2 * t4;
            *(__half2*)(Pw + frow * AV + col)       = __floats2half2_rn(p0, p1);
            *(__half2*)(Pw + (frow + 8) * AV + col) = __floats2half2_rn(p2, p3);
        }
        sum0 += __shfl_xor_sync(0xffffffffu, sum0, 1);
        sum0 += __shfl_xor_sync(0xffffffffu, sum0, 2);
        sum1 += __shfl_xor_sync(0xffffffffu, sum1, 1);
        sum1 += __shfl_xor_sync(0xffffffffu, sum1, 2);
        lrow[0] = lrow[0] * corr0 + sum0;
        lrow[1] = lrow[1] * corr1 + sum1;

        #pragma unroll
        for (int ni = 0; ni < 8; ni++) {
            accO[ni][0] *= corr0; accO[ni][1] *= corr0;
            accO[ni][2] *= corr1; accO[ni][3] *= corr1;
        }
        __syncwarp();

        #pragma unroll
        for (int ks = 0; ks < 8; ks++) {
            const uint32_t kb = ks * 32;
            uint32_t a0, a1, a2, a3;
            ldm_x4(a0, a1, a2, a3, pBase + pOff + kb);
            #pragma unroll
            for (int gg = 0; gg < 2; gg++) {
                uint32_t b0[4], b1[4];
                ldm_x4(b0[0], b0[1], b0[2], b0[3], vBase + vOff[gg] + kb);
                ldm_x4(b1[0], b1[1], b1[2], b1[3], vBase + vOff[gg] + kb + 16);
                #pragma unroll
                for (int j = 0; j < 4; j++)
                    mma_f16(accO[4 * gg + j], a0, a1, a2, a3, b0[j], b1[j]);
            }
        }
    }
    #undef STAGE_KV

    const float inv0 = 1.0f / lrow[0];
    const float inv1 = 1.0f / lrow[1];
    const int r0 = qrow0 + wid * 16 + frow;
    #pragma unroll
    for (int ni = 0; ni < 8; ni++) {
        const int col = h * HD + ni * 8 + 2 * t4;
        *(__half2*)(ctx + (size_t)r0 * D_MODEL + col) =
            __floats2half2_rn(accO[ni][0] * inv0, accO[ni][1] * inv0);
        *(__half2*)(ctx + (size_t)(r0 + 8) * D_MODEL + col) =
            __floats2half2_rn(accO[ni][2] * inv1, accO[ni][3] * inv1);
    }
}

// =================================================================
extern "C" void kernel_launch(void* const* d_in, const int* in_sizes, int n_in,
                              void* d_out, int out_size)
{
    const float* x  = (const float*)d_in[0];
    const float* Wq = (const float*)d_in[1];
    const float* bq = (const float*)d_in[2];
    const float* Wk = (const float*)d_in[3];
    const float* bk = (const float*)d_in[4];
    const float* Wv = (const float*)d_in[5];
    const float* bv = (const float*)d_in[6];
    const float* Wo = (const float*)d_in[7];
    const float* bo = (const float*)d_in[8];
    float* out = (float*)d_out;

    __half *qh, *kh, *vh, *vtg, *ch, *xh, *wt3, *wto;
    cudaGetSymbolAddress((void**)&qh,  g_qh);
    cudaGetSymbolAddress((void**)&kh,  g_kh);
    cudaGetSymbolAddress((void**)&vh,  g_vh);
    cudaGetSymbolAddress((void**)&vtg, g_vt);
    cudaGetSymbolAddress((void**)&ch,  g_ch);
    cudaGetSymbolAddress((void**)&xh,  g_xh);
    cudaGetSymbolAddress((void**)&wt3, g_wt3);
    cudaGetSymbolAddress((void**)&wto, g_wto);

    cudaFuncSetAttribute(attn_h_kernel,
                         cudaFuncAttributeMaxDynamicSharedMemorySize, ATTN_SMEM_BYTES);
    cudaFuncSetAttribute(gemm_h_kernel,
                         cudaFuncAttributeMaxDynamicSharedMemorySize, GEMM_SMEM);

    dim3 tb(32, 8);

    // 1: x -> fp16
    {
        int n4 = MTOT * D_MODEL / 4;
        to_half_kernel<<<(n4 + 255) / 256, 256>>>((const float4*)x, (uint2*)xh, n4);
    }
    // 2-5: all weight transposes (so launch #6 = fused GEMM for ncu)
    transpose_half_kernel<<<dim3(D_MODEL / 32, D_MODEL / 32), tb>>>(Wq, wt3, D_MODEL, D_MODEL);
    transpose_half_kernel<<<dim3(KV_DIM / 32, D_MODEL / 32), tb>>>(
        Wk, wt3 + (size_t)D_MODEL * D_MODEL, D_MODEL, KV_DIM);
    transpose_half_kernel<<<dim3(KV_DIM / 32, D_MODEL / 32), tb>>>(
        Wv, wt3 + (size_t)(D_MODEL + KV_DIM) * D_MODEL, D_MODEL, KV_DIM);
    transpose_half_kernel<<<dim3(D_MODEL / 32, D_MODEL / 32), tb>>>(Wo, wto, D_MODEL, D_MODEL);

    // 6: fused QKV projection
    gemm_h_kernel<<<dim3(NQKV / 128, MTOT / 128), 256, GEMM_SMEM>>>(
        xh, wt3, bq, bk, bv, nullptr, qh, kh, vh, MTOT, NQKV, D_MODEL, 1);

    // 7: V transpose
    vtrans_kernel<<<dim3(SEQ / 32, KV_DIM / 32, BATCH), tb>>>(vh, vtg);

    // 8: attention
    attn_h_kernel<<<dim3(SEQ / 128, NHEADS, BATCH), 256, ATTN_SMEM_BYTES>>>(qh, kh, vtg, ch);

    // 9: output projection (fp32 out)
    gemm_h_kernel<<<dim3(D_MODEL / 128, MTOT / 128), 256, GEMM_SMEM>>>(
        ch, wto, bo, nullptr, nullptr, out, nullptr, nullptr, nullptr,
        MTOT, D_MODEL, D_MODEL, 0);
}

// round 10
// speedup vs baseline: 1.5994x; 1.5994x over previous
#include <cuda_runtime.h>
#include <cuda_fp16.h>
#include <cstdint>

#define D_MODEL 2048
#define KV_DIM  512
#define NHEADS  32
#define NKVH    8
#define HD      64
#define SEQ     1024
#define BATCH   4
#define MTOT    (BATCH * SEQ)   // 4096
#define NQKV    (D_MODEL + 2 * KV_DIM)  // 3072

// ---------------- scratch (no cudaMalloc allowed) ----------------
__device__ __align__(256) __half g_qh[MTOT * D_MODEL];
__device__ __align__(256) __half g_kh[MTOT * KV_DIM];
__device__ __align__(256) __half g_vh[MTOT * KV_DIM];
__device__ __align__(256) __half g_vt[MTOT * KV_DIM];      // V transposed [b][kvh][d][seq]
__device__ __align__(256) __half g_ch[MTOT * D_MODEL];     // attention ctx (fp16)
__device__ __align__(256) __half g_xh[MTOT * D_MODEL];     // x in fp16
__device__ __align__(256) __half g_wt3[NQKV * D_MODEL];    // [Wq;Wk;Wv] transposed fp16
__device__ __align__(256) __half g_wto[D_MODEL * D_MODEL]; // Wo transposed fp16

// ================= helpers =================
__device__ __forceinline__ uint32_t smem_u32(const void* p) {
    uint32_t a;
    asm("{ .reg .u64 t; cvta.to.shared.u64 t, %1; cvt.u32.u64 %0, t; }" : "=r"(a) : "l"(p));
    return a;
}
__device__ __forceinline__ void mma_f16(float c[4], uint32_t a0, uint32_t a1,
                                        uint32_t a2, uint32_t a3,
                                        uint32_t b0, uint32_t b1) {
    asm volatile(
        "mma.sync.aligned.m16n8k16.row.col.f32.f16.f16.f32 "
        "{%0,%1,%2,%3}, {%4,%5,%6,%7}, {%8,%9}, {%0,%1,%2,%3};"
        : "+f"(c[0]), "+f"(c[1]), "+f"(c[2]), "+f"(c[3])
        : "r"(a0), "r"(a1), "r"(a2), "r"(a3), "r"(b0), "r"(b1));
}
__device__ __forceinline__ void ldm_x4(uint32_t& r0, uint32_t& r1,
                                       uint32_t& r2, uint32_t& r3, uint32_t addr) {
    asm volatile("ldmatrix.sync.aligned.m8n8.x4.shared.b16 {%0,%1,%2,%3}, [%4];"
                 : "=r"(r0), "=r"(r1), "=r"(r2), "=r"(r3) : "r"(addr));
}
__device__ __forceinline__ uint32_t packh2(float a, float b) {
    __half2 h = __floats2half2_rn(a, b);
    return *(uint32_t*)&h;
}

// ================= prep kernels =================
__global__ void to_half_kernel(const float4* __restrict__ in, uint2* __restrict__ out, int n4) {
    int i = blockIdx.x * blockDim.x + threadIdx.x;
    if (i < n4) {
        float4 v = in[i];
        __half2 h0 = __floats2half2_rn(v.x, v.y);
        __half2 h1 = __floats2half2_rn(v.z, v.w);
        out[i] = make_uint2(*(uint32_t*)&h0, *(uint32_t*)&h1);
    }
}

// W [K, N] fp32 row-major -> Wt [N, K] fp16 row-major
__global__ void transpose_half_kernel(const float* __restrict__ W, __half* __restrict__ Wt,
                                      int K, int N) {
    __shared__ float t[32][33];
    const int n0 = blockIdx.x * 32, k0 = blockIdx.y * 32;
    const int tx = threadIdx.x, ty = threadIdx.y;  // 32 x 8
    #pragma unroll
    for (int i = 0; i < 32; i += 8)
        t[ty + i][tx] = W[(size_t)(k0 + ty + i) * N + n0 + tx];
    __syncthreads();
    #pragma unroll
    for (int i = 0; i < 32; i += 8)
        Wt[(size_t)(n0 + ty + i) * K + k0 + tx] = __float2half_rn(t[tx][ty + i]);
}

// v [MTOT][KV_DIM] fp16 -> vt [(b*KV_DIM + c)][SEQ] fp16
__global__ void vtrans_kernel(const __half* __restrict__ v, __half* __restrict__ vt) {
    __shared__ __half t[32][34];
    const int s0 = blockIdx.x * 32, c0 = blockIdx.y * 32, b = blockIdx.z;
    const int tx = threadIdx.x, ty = threadIdx.y;  // 32 x 8
    #pragma unroll
    for (int i = 0; i < 32; i += 8)
        t[ty + i][tx] = v[(size_t)(b * SEQ + s0 + ty + i) * KV_DIM + c0 + tx];
    __syncthreads();
    #pragma unroll
    for (int i = 0; i < 32; i += 8)
        vt[(size_t)(b * KV_DIM + c0 + ty + i) * SEQ + s0 + tx] = t[tx][ty + i];
}

// ================= fp16 warp-MMA GEMM (ldmatrix, 3-stage) =================
// 128x128 tile, BK=64 halfs, 8 warps (2x4 -> 64x32 each). Pitch 72 halfs.
// mode 1: fused QKV — route output block to q/k/v fp16 buffers by column.
// mode 0: fp32 output + single bias.
#define GS   3
#define GPH  72
#define GA_STAGE (128 * GPH)            // halfs
#define GSTAGE_H (2 * 128 * GPH)
#define GEMM_SMEM (GS * GSTAGE_H * 2)   // 110592 B

__global__ __launch_bounds__(256, 2) void gemm_h_kernel(
    const __half* __restrict__ A, const __half* __restrict__ Bt,
    const float* __restrict__ bias0, const float* __restrict__ bias1,
    const float* __restrict__ bias2,
    float* __restrict__ outF,
    __half* __restrict__ outQ, __half* __restrict__ outK, __half* __restrict__ outV,
    int M, int N, int K, int mode)
{
    extern __shared__ __align__(16) __half hsm[];

    const int tid  = threadIdx.x;
    const int wid  = tid >> 5;
    const int lane = tid & 31;
    const int m0 = blockIdx.y * 128;
    const int n0 = blockIdx.x * 128;
    const int wm = wid & 1;
    const int wn = wid >> 1;
    const int frow = lane >> 2;
    const int t4   = lane & 3;

    const bool isA = tid < 128;
    const int  row = isA ? tid : tid - 128;
    const __half* gsrc = isA ? (A + (size_t)(m0 + row) * K)
                             : (Bt + (size_t)(n0 + row) * K);
    const uint32_t smem_base = smem_u32(hsm);
    const uint32_t sdst_row = smem_base + ((isA ? 0 : GA_STAGE) + row * GPH) * 2;

    // ldmatrix lane offsets (bytes, relative to stage base)
    uint32_t aOff[4];
    #pragma unroll
    for (int mi = 0; mi < 4; mi++)
        aOff[mi] = ((wm * 64 + mi * 16 + (lane & 15)) * GPH + (lane >> 4) * 8) * 2;
    const uint32_t bOff = ((wn * 32 + (lane >> 3) * 8 + (lane & 7)) * GPH) * 2;

    const int nChunks = K / 64;

    #define GISSUE(ch, st) do {                                                \
        uint32_t _d = sdst_row + (st) * (GSTAGE_H * 2);                        \
        const __half* _g = gsrc + (ch) * 64;                                   \
        _Pragma("unroll")                                                      \
        for (int _c = 0; _c < 8; _c++)                                         \
            asm volatile("cp.async.cg.shared.global [%0], [%1], 16;"           \
                         :: "r"(_d + _c * 16), "l"(_g + _c * 8) : "memory");   \
    } while (0)

    GISSUE(0, 0);
    asm volatile("cp.async.commit_group;" ::: "memory");
    GISSUE(1, 1);
    asm volatile("cp.async.commit_group;" ::: "memory");

    float acc[4][4][4];
    #pragma unroll
    for (int mi = 0; mi < 4; mi++)
        #pragma unroll
        for (int ni = 0; ni < 4; ni++)
            #pragma unroll
            for (int r = 0; r < 4; r++) acc[mi][ni][r] = 0.f;

    for (int ch = 0; ch < nChunks; ch++) {
        asm volatile("cp.async.wait_group 1;" ::: "memory");
        __syncthreads();
        if (ch + 2 < nChunks) GISSUE(ch + 2, (ch + 2) % GS);
        asm volatile("cp.async.commit_group;" ::: "memory");

        const uint32_t stA = smem_base + (ch % GS) * (GSTAGE_H * 2);
        const uint32_t stB = stA + GA_STAGE * 2;

        #pragma unroll
        for (int ks = 0; ks < 4; ks++) {
            const uint32_t kb = ks * 32;   // bytes
            uint32_t a[4][4], b0[4], b1[4];
            #pragma unroll
            for (int mi = 0; mi < 4; mi++)
                ldm_x4(a[mi][0], a[mi][1], a[mi][2], a[mi][3], stA + aOff[mi] + kb);
            ldm_x4(b0[0], b0[1], b0[2], b0[3], stB + bOff + kb);
            ldm_x4(b1[0], b1[1], b1[2], b1[3], stB + bOff + kb + 16);
            #pragma unroll
            for (int mi = 0; mi < 4; mi++)
                #pragma unroll
                for (int ni = 0; ni < 4; ni++)
                    mma_f16(acc[mi][ni], a[mi][0], a[mi][1], a[mi][2], a[mi][3],
                            b0[ni], b1[ni]);
        }
    }
    #undef GISSUE

    // ---- epilogue ----
    const float* bias = bias0;
    __half* dstH = outQ;
    int colbase = n0, stride = N;
    if (mode == 1) {
        if (n0 < D_MODEL)               { dstH = outQ; bias = bias0; colbase = n0;              stride = D_MODEL; }
        else if (n0 < D_MODEL + KV_DIM) { dstH = outK; bias = bias1; colbase = n0 - D_MODEL;    stride = KV_DIM; }
        else                            { dstH = outV; bias = bias2; colbase = n0 - D_MODEL - KV_DIM; stride = KV_DIM; }
    }

    #pragma unroll
    for (int mi = 0; mi < 4; mi++) {
        const int r0 = m0 + wm * 64 + mi * 16 + frow;
        #pragma unroll
        for (int ni = 0; ni < 4; ni++) {
            const int col = colbase + wn * 32 + ni * 8 + 2 * t4;
            const float b0 = bias[col], b1 = bias[col + 1];
            const float v00 = acc[mi][ni][0] + b0, v01 = acc[mi][ni][1] + b1;
            const float v10 = acc[mi][ni][2] + b0, v11 = acc[mi][ni][3] + b1;
            if (mode == 1) {
                *(__half2*)(dstH + (size_t)r0 * stride + col) = __floats2half2_rn(v00, v01);
                *(__half2*)(dstH + (size_t)(r0 + 8) * stride + col) = __floats2half2_rn(v10, v11);
            } else {
                *(float2*)(outF + (size_t)r0 * stride + col) = make_float2(v00, v01);
                *(float2*)(outF + (size_t)(r0 + 8) * stride + col) = make_float2(v10, v11);
            }
        }
    }
}

// =================================================================
// fp16 flash attention: ldmatrix, double-buffered K/V, P kept in
// registers (S-accum fragment layout == PV A-fragment layout).
// =================================================================
#define AQ 72      // Q/K pitch (halfs): 144 B
#define AV 136     // Vt pitch (halfs): 272 B
#define KT_HALFS (128 * AQ)
#define VT_HALFS (64 * AV)
#define SQ 0
#define SK0 (SQ + 128 * AQ)
#define SV0 (SK0 + 2 * KT_HALFS)
#define ATTN_HALFS (SV0 + 2 * VT_HALFS)
#define ATTN_SMEM_BYTES (ATTN_HALFS * 2)   // 90112 B

__global__ __launch_bounds__(256) void attn_h_kernel(
    const __half* __restrict__ q, const __half* __restrict__ k,
    const __half* __restrict__ vt, __half* __restrict__ ctx)
{
    extern __shared__ __align__(16) __half hsm[];

    const int tid  = threadIdx.x;
    const int wid  = tid >> 5;
    const int lane = tid & 31;
    const int frow = lane >> 2;
    const int t4   = lane & 3;
    const int qt = blockIdx.x;
    const int h  = blockIdx.y;
    const int b  = blockIdx.z;
    const int kvh = h >> 2;

    const int qrow0 = b * SEQ + qt * 128;
    const __half* qbase = q + (size_t)qrow0 * D_MODEL + h * HD;
    const __half* kbase = k + (size_t)b * SEQ * KV_DIM + kvh * HD;
    const __half* vtbase = vt + (size_t)(b * KV_DIM + kvh * HD) * SEQ;

    const uint32_t smb = smem_u32(hsm);
    const int srow = tid >> 1;
    const int sc   = (tid & 1) * 32;
    const int vrow = tid >> 2;
    const int vc   = (tid & 3) * 32;

    {
        const __half* g = qbase + (size_t)srow * D_MODEL + sc;
        uint32_t d = smb + (SQ + srow * AQ + sc) * 2;
        #pragma unroll
        for (int c = 0; c < 4; c++)
            asm volatile("cp.async.cg.shared.global [%0], [%1], 16;"
                         :: "r"(d + c * 16), "l"(g + c * 8) : "memory");
        asm volatile("cp.async.commit_group;" ::: "memory");
    }

    #define STAGE_KV(kt, buf) do {                                             \
        const __half* gk = kbase + (size_t)((kt) * 128 + srow) * KV_DIM + sc;  \
        uint32_t dk = smb + (SK0 + (buf) * KT_HALFS + srow * AQ + sc) * 2;     \
        _Pragma("unroll")                                                      \
        for (int c = 0; c < 4; c++)                                            \
            asm volatile("cp.async.cg.shared.global [%0], [%1], 16;"           \
                         :: "r"(dk + c * 16), "l"(gk + c * 8) : "memory");     \
        const __half* gv = vtbase + (size_t)vrow * SEQ + (kt) * 128 + vc;      \
        uint32_t dv = smb + (SV0 + (buf) * VT_HALFS + vrow * AV + vc) * 2;     \
        _Pragma("unroll")                                                      \
        for (int c = 0; c < 4; c++)                                            \
            asm volatile("cp.async.cg.shared.global [%0], [%1], 16;"           \
                         :: "r"(dv + c * 16), "l"(gv + c * 8) : "memory");     \
    } while (0)

    STAGE_KV(0, 0);
    asm volatile("cp.async.commit_group;" ::: "memory");

    const uint32_t qOff = ((wid * 16 + (lane & 15)) * AQ + (lane >> 4) * 8) * 2;
    uint32_t kOff[4], vOff[2];
    #pragma unroll
    for (int gg = 0; gg < 4; gg++)
        kOff[gg] = (((4 * gg + (lane >> 3)) * 8 + (lane & 7)) * AQ) * 2;
    #pragma unroll
    for (int gg = 0; gg < 2; gg++)
        vOff[gg] = (((4 * gg + (lane >> 3)) * 8 + (lane & 7)) * AV) * 2;

    float mrow[2] = {-1e30f, -1e30f};
    float lrow[2] = {0.f, 0.f};
    float accO[8][4];
    #pragma unroll
    for (int ni = 0; ni < 8; ni++)
        #pragma unroll
        for (int r = 0; r < 4; r++) accO[ni][r] = 0.f;

    for (int kt = 0; kt < SEQ / 128; kt++) {
        __syncthreads();   // all warps done reading the buffer about to be refilled
        if (kt + 1 < SEQ / 128) STAGE_KV(kt + 1, (kt + 1) & 1);
        asm volatile("cp.async.commit_group;" ::: "memory");
        asm volatile("cp.async.wait_group 1;" ::: "memory");
        __syncthreads();   // kt's K/V visible

        const uint32_t kBase = smb + (SK0 + (kt & 1) * KT_HALFS) * 2;
        const uint32_t vBase = smb + (SV0 + (kt & 1) * VT_HALFS) * 2;
        const uint32_t qBase = smb + SQ * 2;

        // ---- S = Q @ K^T (16 q-rows x 128 keys, K = 64 = 4 k16 steps) ----
        float accS[16][4];
        #pragma unroll
        for (int ni = 0; ni < 16; ni++)
            #pragma unroll
            for (int r = 0; r < 4; r++) accS[ni][r] = 0.f;

        #pragma unroll
        for (int ks = 0; ks < 4; ks++) {
            const uint32_t kb = ks * 32;
            uint32_t a0, a1, a2, a3;
            ldm_x4(a0, a1, a2, a3, qBase + qOff + kb);
            #pragma unroll
            for (int gg = 0; gg < 4; gg++) {
                uint32_t b0[4], b1[4];
                ldm_x4(b0[0], b0[1], b0[2], b0[3], kBase + kOff[gg] + kb);
                ldm_x4(b1[0], b1[1], b1[2], b1[3], kBase + kOff[gg] + kb + 16);
                #pragma unroll
                for (int j = 0; j < 4; j++)
                    mma_f16(accS[4 * gg + j], a0, a1, a2, a3, b0[j], b1[j]);
            }
        }

        // ---- streaming softmax (rows frow, frow+8 of this warp) ----
        float mx0 = -1e30f, mx1 = -1e30f;
        #pragma unroll
        for (int ni = 0; ni < 16; ni++) {
            #pragma unroll
            for (int r = 0; r < 4; r++) accS[ni][r] *= 0.125f;
            mx0 = fmaxf(mx0, fmaxf(accS[ni][0], accS[ni][1]));
            mx1 = fmaxf(mx1, fmaxf(accS[ni][2], accS[ni][3]));
        }
        mx0 = fmaxf(mx0, __shfl_xor_sync(0xffffffffu, mx0, 1));
        mx0 = fmaxf(mx0, __shfl_xor_sync(0xffffffffu, mx0, 2));
        mx1 = fmaxf(mx1, __shfl_xor_sync(0xffffffffu, mx1, 1));
        mx1 = fmaxf(mx1, __shfl_xor_sync(0xffffffffu, mx1, 2));

        const float mn0 = fmaxf(mrow[0], mx0);
        const float mn1 = fmaxf(mrow[1], mx1);
        const float corr0 = __expf(mrow[0] - mn0);
        const float corr1 = __expf(mrow[1] - mn1);
        mrow[0] = mn0; mrow[1] = mn1;

        // exp + pack P directly into A-fragments for the PV mma
        uint32_t pa[8][4];
        float sum0 = 0.f, sum1 = 0.f;
        #pragma unroll
        for (int ni = 0; ni < 16; ni++) {
            float p0 = __expf(accS[ni][0] - mn0);
            float p1 = __expf(accS[ni][1] - mn0);
            float p2 = __expf(accS[ni][2] - mn1);
            float p3 = __expf(accS[ni][3] - mn1);
            sum0 += p0 + p1;
            sum1 += p2 + p3;
            const int ks = ni >> 1;
            if (ni & 1) { pa[ks][2] = packh2(p0, p1); pa[ks][3] = packh2(p2, p3); }
            else        { pa[ks][0] = packh2(p0, p1); pa[ks][1] = packh2(p2, p3); }
        }
        sum0 += __shfl_xor_sync(0xffffffffu, sum0, 1);
        sum0 += __shfl_xor_sync(0xffffffffu, sum0, 2);
        sum1 += __shfl_xor_sync(0xffffffffu, sum1, 1);
        sum1 += __shfl_xor_sync(0xffffffffu, sum1, 2);
        lrow[0] = lrow[0] * corr0 + sum0;
        lrow[1] = lrow[1] * corr1 + sum1;

        #pragma unroll
        for (int ni = 0; ni < 8; ni++) {
            accO[ni][0] *= corr0; accO[ni][1] *= corr0;
            accO[ni][2] *= corr1; accO[ni][3] *= corr1;
        }

        // ---- O += P @ V (16 rows x 64 d, K = 128 keys = 8 k16 steps) ----
        #pragma unroll
        for (int ks = 0; ks < 8; ks++) {
            const uint32_t kb = ks * 32;
            #pragma unroll
            for (int gg = 0; gg < 2; gg++) {
                uint32_t b0[4], b1[4];
                ldm_x4(b0[0], b0[1], b0[2], b0[3], vBase + vOff[gg] + kb);
                ldm_x4(b1[0], b1[1], b1[2], b1[3], vBase + vOff[gg] + kb + 16);
                #pragma unroll
                for (int j = 0; j < 4; j++)
                    mma_f16(accO[4 * gg + j], pa[ks][0], pa[ks][1], pa[ks][2], pa[ks][3],
                            b0[j], b1[j]);
            }
        }
    }
    #undef STAGE_KV

    const float inv0 = 1.0f / lrow[0];
    const float inv1 = 1.0f / lrow[1];
    const int r0 = qrow0 + wid * 16 + frow;
    #pragma unroll
    for (int ni = 0; ni < 8; ni++) {
        const int col = h * HD + ni * 8 + 2 * t4;
        *(__half2*)(ctx + (size_t)r0 * D_MODEL + col) =
            __floats2half2_rn(accO[ni][0] * inv0, accO[ni][1] * inv0);
        *(__half2*)(ctx + (size_t)(r0 + 8) * D_MODEL + col) =
            __floats2half2_rn(accO[ni][2] * inv1, accO[ni][3] * inv1);
    }
}

// =================================================================
extern "C" void kernel_launch(void* const* d_in, const int* in_sizes, int n_in,
                              void* d_out, int out_size)
{
    const float* x  = (const float*)d_in[0];
    const float* Wq = (const float*)d_in[1];
    const float* bq = (const float*)d_in[2];
    const float* Wk = (const float*)d_in[3];
    const float* bk = (const float*)d_in[4];
    const float* Wv = (const float*)d_in[5];
    const float* bv = (const float*)d_in[6];
    const float* Wo = (const float*)d_in[7];
    const float* bo = (const float*)d_in[8];
    float* out = (float*)d_out;

    __half *qh, *kh, *vh, *vtg, *ch, *xh, *wt3, *wto;
    cudaGetSymbolAddress((void**)&qh,  g_qh);
    cudaGetSymbolAddress((void**)&kh,  g_kh);
    cudaGetSymbolAddress((void**)&vh,  g_vh);
    cudaGetSymbolAddress((void**)&vtg, g_vt);
    cudaGetSymbolAddress((void**)&ch,  g_ch);
    cudaGetSymbolAddress((void**)&xh,  g_xh);
    cudaGetSymbolAddress((void**)&wt3, g_wt3);
    cudaGetSymbolAddress((void**)&wto, g_wto);

    cudaFuncSetAttribute(attn_h_kernel,
                         cudaFuncAttributeMaxDynamicSharedMemorySize, ATTN_SMEM_BYTES);
    cudaFuncSetAttribute(gemm_h_kernel,
                         cudaFuncAttributeMaxDynamicSharedMemorySize, GEMM_SMEM);

    dim3 tb(32, 8);

    // 1: x -> fp16
    {
        int n4 = MTOT * D_MODEL / 4;
        to_half_kernel<<<(n4 + 255) / 256, 256>>>((const float4*)x, (uint2*)xh, n4);
    }
    // 2-5: weight transposes
    transpose_half_kernel<<<dim3(D_MODEL / 32, D_MODEL / 32), tb>>>(Wq, wt3, D_MODEL, D_MODEL);
    transpose_half_kernel<<<dim3(KV_DIM / 32, D_MODEL / 32), tb>>>(
        Wk, wt3 + (size_t)D_MODEL * D_MODEL, D_MODEL, KV_DIM);
    transpose_half_kernel<<<dim3(KV_DIM / 32, D_MODEL / 32), tb>>>(
        Wv, wt3 + (size_t)(D_MODEL + KV_DIM) * D_MODEL, D_MODEL, KV_DIM);
    transpose_half_kernel<<<dim3(D_MODEL / 32, D_MODEL / 32), tb>>>(Wo, wto, D_MODEL, D_MODEL);

    // 6: fused QKV projection
    gemm_h_kernel<<<dim3(NQKV / 128, MTOT / 128), 256, GEMM_SMEM>>>(
        xh, wt3, bq, bk, bv, nullptr, qh, kh, vh, MTOT, NQKV, D_MODEL, 1);

    // 7: V transpose
    vtrans_kernel<<<dim3(SEQ / 32, KV_DIM / 32, BATCH), tb>>>(vh, vtg);

    // 8: attention
    attn_h_kernel<<<dim3(SEQ / 128, NHEADS, BATCH), 256, ATTN_SMEM_BYTES>>>(qh, kh, vtg, ch);

    // 9: output projection (fp32 out)
    gemm_h_kernel<<<dim3(D_MODEL / 128, MTOT / 128), 256, GEMM_SMEM>>>(
        ch, wto, bo, nullptr, nullptr, out, nullptr, nullptr, nullptr,
        MTOT, D_MODEL, D_MODEL, 0);
}

// round 12
// speedup vs baseline: 1.6225x; 1.0144x over previous
#include <cuda_runtime.h>
#include <cuda_fp16.h>
#include <cstdint>

#define D_MODEL 2048
#define KV_DIM  512
#define NHEADS  32
#define NKVH    8
#define HD      64
#define SEQ     1024
#define BATCH   4
#define MTOT    (BATCH * SEQ)   // 4096
#define NQKV    (D_MODEL + 2 * KV_DIM)  // 3072

// ---------------- scratch (no cudaMalloc allowed) ----------------
__device__ __align__(256) __half g_qh[MTOT * D_MODEL];
__device__ __align__(256) __half g_kh[MTOT * KV_DIM];
__device__ __align__(256) __half g_vh[MTOT * KV_DIM];
__device__ __align__(256) __half g_ch[MTOT * D_MODEL];     // attention ctx (fp16)
__device__ __align__(256) __half g_xh[MTOT * D_MODEL];     // x in fp16
__device__ __align__(256) __half g_wt3[NQKV * D_MODEL];    // [Wq;Wk;Wv] transposed fp16
__device__ __align__(256) __half g_wto[D_MODEL * D_MODEL]; // Wo transposed fp16

// ================= helpers =================
__device__ __forceinline__ uint32_t smem_u32(const void* p) {
    uint32_t a;
    asm("{ .reg .u64 t; cvta.to.shared.u64 t, %1; cvt.u32.u64 %0, t; }" : "=r"(a) : "l"(p));
    return a;
}
__device__ __forceinline__ void mma_f16(float c[4], uint32_t a0, uint32_t a1,
                                        uint32_t a2, uint32_t a3,
                                        uint32_t b0, uint32_t b1) {
    asm volatile(
        "mma.sync.aligned.m16n8k16.row.col.f32.f16.f16.f32 "
        "{%0,%1,%2,%3}, {%4,%5,%6,%7}, {%8,%9}, {%0,%1,%2,%3};"
        : "+f"(c[0]), "+f"(c[1]), "+f"(c[2]), "+f"(c[3])
        : "r"(a0), "r"(a1), "r"(a2), "r"(a3), "r"(b0), "r"(b1));
}
__device__ __forceinline__ void ldm_x4(uint32_t& r0, uint32_t& r1,
                                       uint32_t& r2, uint32_t& r3, uint32_t addr) {
    asm volatile("ldmatrix.sync.aligned.m8n8.x4.shared.b16 {%0,%1,%2,%3}, [%4];"
                 : "=r"(r0), "=r"(r1), "=r"(r2), "=r"(r3) : "r"(addr));
}
__device__ __forceinline__ void ldm_x4t(uint32_t& r0, uint32_t& r1,
                                        uint32_t& r2, uint32_t& r3, uint32_t addr) {
    asm volatile("ldmatrix.sync.aligned.m8n8.x4.trans.shared.b16 {%0,%1,%2,%3}, [%4];"
                 : "=r"(r0), "=r"(r1), "=r"(r2), "=r"(r3) : "r"(addr));
}
__device__ __forceinline__ uint32_t packh2(float a, float b) {
    __half2 h = __floats2half2_rn(a, b);
    return *(uint32_t*)&h;
}

// ================= prep kernels =================
__global__ void to_half_kernel(const float4* __restrict__ in, uint2* __restrict__ out, int n4) {
    int i = blockIdx.x * blockDim.x + threadIdx.x;
    if (i < n4) {
        float4 v = in[i];
        __half2 h0 = __floats2half2_rn(v.x, v.y);
        __half2 h1 = __floats2half2_rn(v.z, v.w);
        out[i] = make_uint2(*(uint32_t*)&h0, *(uint32_t*)&h1);
    }
}

// Fused Wq/Wk/Wv transpose: W [2048, N] fp32 -> wt3 region [N, 2048] fp16
__global__ void transpose3_kernel(const float* __restrict__ Wq, const float* __restrict__ Wk,
                                  const float* __restrict__ Wv, __half* __restrict__ wt3) {
    __shared__ float t[32][33];
    const int z = blockIdx.z;
    const float* W;
    __half* dst;
    int N;
    if (z == 0)      { W = Wq; N = D_MODEL; dst = wt3; }
    else if (z == 1) { W = Wk; N = KV_DIM;  dst = wt3 + (size_t)D_MODEL * D_MODEL; }
    else             { W = Wv; N = KV_DIM;  dst = wt3 + (size_t)(D_MODEL + KV_DIM) * D_MODEL; }
    const int n0 = blockIdx.x * 32;
    if (n0 >= N) return;
    const int k0 = blockIdx.y * 32;
    const int tx = threadIdx.x, ty = threadIdx.y;  // 32 x 8
    #pragma unroll
    for (int i = 0; i < 32; i += 8)
        t[ty + i][tx] = W[(size_t)(k0 + ty + i) * N + n0 + tx];
    __syncthreads();
    #pragma unroll
    for (int i = 0; i < 32; i += 8)
        dst[(size_t)(n0 + ty + i) * D_MODEL + k0 + tx] = __float2half_rn(t[tx][ty + i]);
}

// W [K, N] fp32 row-major -> Wt [N, K] fp16 row-major
__global__ void transpose_half_kernel(const float* __restrict__ W, __half* __restrict__ Wt,
                                      int K, int N) {
    __shared__ float t[32][33];
    const int n0 = blockIdx.x * 32, k0 = blockIdx.y * 32;
    const int tx = threadIdx.x, ty = threadIdx.y;  // 32 x 8
    #pragma unroll
    for (int i = 0; i < 32; i += 8)
        t[ty + i][tx] = W[(size_t)(k0 + ty + i) * N + n0 + tx];
    __syncthreads();
    #pragma unroll
    for (int i = 0; i < 32; i += 8)
        Wt[(size_t)(n0 + ty + i) * K + k0 + tx] = __float2half_rn(t[tx][ty + i]);
}

// ================= fp16 warp-MMA GEMM (ldmatrix, 3-stage) =================
// 128x128 tile, BK=64 halfs, 8 warps (2x4 -> 64x32 each). Pitch 72 halfs.
// mode 1: fused QKV — route output block to q/k/v fp16 buffers by column.
// mode 0: fp32 output + single bias.
#define GS   3
#define GPH  72
#define GA_STAGE (128 * GPH)            // halfs
#define GSTAGE_H (2 * 128 * GPH)
#define GEMM_SMEM (GS * GSTAGE_H * 2)   // 110592 B

__global__ __launch_bounds__(256, 2) void gemm_h_kernel(
    const __half* __restrict__ A, const __half* __restrict__ Bt,
    const float* __restrict__ bias0, const float* __restrict__ bias1,
    const float* __restrict__ bias2,
    float* __restrict__ outF,
    __half* __restrict__ outQ, __half* __restrict__ outK, __half* __restrict__ outV,
    int M, int N, int K, int mode)
{
    extern __shared__ __align__(16) __half hsm[];

    const int tid  = threadIdx.x;
    const int wid  = tid >> 5;
    const int lane = tid & 31;
    const int m0 = blockIdx.y * 128;
    const int n0 = blockIdx.x * 128;
    const int wm = wid & 1;
    const int wn = wid >> 1;
    const int frow = lane >> 2;
    const int t4   = lane & 3;

    const bool isA = tid < 128;
    const int  row = isA ? tid : tid - 128;
    const __half* gsrc = isA ? (A + (size_t)(m0 + row) * K)
                             : (Bt + (size_t)(n0 + row) * K);
    const uint32_t smem_base = smem_u32(hsm);
    const uint32_t sdst_row = smem_base + ((isA ? 0 : GA_STAGE) + row * GPH) * 2;

    // ldmatrix lane offsets (bytes, relative to stage base)
    uint32_t aOff[4];
    #pragma unroll
    for (int mi = 0; mi < 4; mi++)
        aOff[mi] = ((wm * 64 + mi * 16 + (lane & 15)) * GPH + (lane >> 4) * 8) * 2;
    const uint32_t bOff = ((wn * 32 + (lane >> 3) * 8 + (lane & 7)) * GPH) * 2;

    const int nChunks = K / 64;

    #define GISSUE(ch, st) do {                                                \
        uint32_t _d = sdst_row + (st) * (GSTAGE_H * 2);                        \
        const __half* _g = gsrc + (ch) * 64;                                   \
        _Pragma("unroll")                                                      \
        for (int _c = 0; _c < 8; _c++)                                         \
            asm volatile("cp.async.cg.shared.global [%0], [%1], 16;"           \
                         :: "r"(_d + _c * 16), "l"(_g + _c * 8) : "memory");   \
    } while (0)

    GISSUE(0, 0);
    asm volatile("cp.async.commit_group;" ::: "memory");
    GISSUE(1, 1);
    asm volatile("cp.async.commit_group;" ::: "memory");

    float acc[4][4][4];
    #pragma unroll
    for (int mi = 0; mi < 4; mi++)
        #pragma unroll
        for (int ni = 0; ni < 4; ni++)
            #pragma unroll
            for (int r = 0; r < 4; r++) acc[mi][ni][r] = 0.f;

    for (int ch = 0; ch < nChunks; ch++) {
        asm volatile("cp.async.wait_group 1;" ::: "memory");
        __syncthreads();
        if (ch + 2 < nChunks) GISSUE(ch + 2, (ch + 2) % GS);
        asm volatile("cp.async.commit_group;" ::: "memory");

        const uint32_t stA = smem_base + (ch % GS) * (GSTAGE_H * 2);
        const uint32_t stB = stA + GA_STAGE * 2;

        #pragma unroll
        for (int ks = 0; ks < 4; ks++) {
            const uint32_t kb = ks * 32;   // bytes
            uint32_t a[4][4], b0[4], b1[4];
            #pragma unroll
            for (int mi = 0; mi < 4; mi++)
                ldm_x4(a[mi][0], a[mi][1], a[mi][2], a[mi][3], stA + aOff[mi] + kb);
            ldm_x4(b0[0], b0[1], b0[2], b0[3], stB + bOff + kb);
            ldm_x4(b1[0], b1[1], b1[2], b1[3], stB + bOff + kb + 16);
            #pragma unroll
            for (int mi = 0; mi < 4; mi++)
                #pragma unroll
                for (int ni = 0; ni < 4; ni++)
                    mma_f16(acc[mi][ni], a[mi][0], a[mi][1], a[mi][2], a[mi][3],
                            b0[ni], b1[ni]);
        }
    }
    #undef GISSUE

    // ---- epilogue ----
    const float* bias = bias0;
    __half* dstH = outQ;
    int colbase = n0, stride = N;
    if (mode == 1) {
        if (n0 < D_MODEL)               { dstH = outQ; bias = bias0; colbase = n0;              stride = D_MODEL; }
        else if (n0 < D_MODEL + KV_DIM) { dstH = outK; bias = bias1; colbase = n0 - D_MODEL;    stride = KV_DIM; }
        else                            { dstH = outV; bias = bias2; colbase = n0 - D_MODEL - KV_DIM; stride = KV_DIM; }
    }

    #pragma unroll
    for (int mi = 0; mi < 4; mi++) {
        const int r0 = m0 + wm * 64 + mi * 16 + frow;
        #pragma unroll
        for (int ni = 0; ni < 4; ni++) {
            const int col = colbase + wn * 32 + ni * 8 + 2 * t4;
            const float b0 = bias[col], b1 = bias[col + 1];
            const float v00 = acc[mi][ni][0] + b0, v01 = acc[mi][ni][1] + b1;
            const float v10 = acc[mi][ni][2] + b0, v11 = acc[mi][ni][3] + b1;
            if (mode == 1) {
                *(__half2*)(dstH + (size_t)r0 * stride + col) = __floats2half2_rn(v00, v01);
                *(__half2*)(dstH + (size_t)(r0 + 8) * stride + col) = __floats2half2_rn(v10, v11);
            } else {
                *(float2*)(outF + (size_t)r0 * stride + col) = make_float2(v00, v01);
                *(float2*)(outF + (size_t)(r0 + 8) * stride + col) = make_float2(v10, v11);
            }
        }
    }
}

// =================================================================
// fp16 flash attention: ldmatrix (+trans for V), double-buffered K/V,
// P kept in registers, Q fragments hoisted out of the kt loop.
// K and V both staged [key][d] at pitch 72.
// =================================================================
#define AQ 72      // Q/K/V pitch (halfs): 144 B
#define KT_HALFS (128 * AQ)   // 9216 per K or V buffer
#define SQ 0
#define SK0 (SQ + 128 * AQ)
#define SV0 (SK0 + 2 * KT_HALFS)
#define ATTN_HALFS (SV0 + 2 * KT_HALFS)
#define ATTN_SMEM_BYTES (ATTN_HALFS * 2)   // 92160 B

__global__ __launch_bounds__(256) void attn_h_kernel(
    const __half* __restrict__ q, const __half* __restrict__ k,
    const __half* __restrict__ v, __half* __restrict__ ctx)
{
    extern __shared__ __align__(16) __half hsm[];

    const int tid  = threadIdx.x;
    const int wid  = tid >> 5;
    const int lane = tid & 31;
    const int frow = lane >> 2;
    const int t4   = lane & 3;
    const int qt = blockIdx.x;
    const int h  = blockIdx.y;
    const int b  = blockIdx.z;
    const int kvh = h >> 2;

    const int qrow0 = b * SEQ + qt * 128;
    const __half* qbase = q + (size_t)qrow0 * D_MODEL + h * HD;
    const __half* kbase = k + (size_t)b * SEQ * KV_DIM + kvh * HD;
    const __half* vbase = v + (size_t)b * SEQ * KV_DIM + kvh * HD;

    const uint32_t smb = smem_u32(hsm);
    const int srow = tid >> 1;          // 0..127
    const int sc   = (tid & 1) * 32;    // halfs

    // ---- stage Q (own group) ----
    {
        const __half* g = qbase + (size_t)srow * D_MODEL + sc;
        uint32_t d = smb + (SQ + srow * AQ + sc) * 2;
        #pragma unroll
        for (int c = 0; c < 4; c++)
            asm volatile("cp.async.cg.shared.global [%0], [%1], 16;"
                         :: "r"(d + c * 16), "l"(g + c * 8) : "memory");
        asm volatile("cp.async.commit_group;" ::: "memory");
    }

    #define STAGE_KV(kt, buf) do {                                             \
        const __half* gk = kbase + (size_t)((kt) * 128 + srow) * KV_DIM + sc;  \
        uint32_t dk = smb + (SK0 + (buf) * KT_HALFS + srow * AQ + sc) * 2;     \
        _Pragma("unroll")                                                      \
        for (int c = 0; c < 4; c++)                                            \
            asm volatile("cp.async.cg.shared.global [%0], [%1], 16;"           \
                         :: "r"(dk + c * 16), "l"(gk + c * 8) : "memory");     \
        const __half* gv = vbase + (size_t)((kt) * 128 + srow) * KV_DIM + sc;  \
        uint32_t dv = smb + (SV0 + (buf) * KT_HALFS + srow * AQ + sc) * 2;     \
        _Pragma("unroll")                                                      \
        for (int c = 0; c < 4; c++)                                            \
            asm volatile("cp.async.cg.shared.global [%0], [%1], 16;"           \
                         :: "r"(dv + c * 16), "l"(gv + c * 8) : "memory");     \
    } while (0)

    STAGE_KV(0, 0);
    asm volatile("cp.async.commit_group;" ::: "memory");

    // ldmatrix lane offsets (bytes)
    const uint32_t qOff = ((wid * 16 + (lane & 15)) * AQ + (lane >> 4) * 8) * 2;
    uint32_t kOff[4];
    #pragma unroll
    for (int gg = 0; gg < 4; gg++)
        kOff[gg] = (((4 * gg + (lane >> 3)) * 8 + (lane & 7)) * AQ) * 2;
    // V trans-frag offsets: group g covers d-cols [16g, 16g+16); lanes:
    // row = (lane&7) + 8*((lane>>3)&1)  (keys), col = (2g + (lane>>4))*8 (d)
    uint32_t vOff[4];
    #pragma unroll
    for (int gg = 0; gg < 4; gg++) {
        const int vr = (lane & 7) + 8 * ((lane >> 3) & 1);
        const int vcd = (2 * gg + (lane >> 4)) * 8;
        vOff[gg] = (vr * AQ + vcd) * 2;
    }

    // wait for Q (newest group = KV0 may still be in flight), hoist Q frags
    asm volatile("cp.async.wait_group 1;" ::: "memory");
    __syncthreads();
    uint32_t qa[4][4];
    #pragma unroll
    for (int ks = 0; ks < 4; ks++)
        ldm_x4(qa[ks][0], qa[ks][1], qa[ks][2], qa[ks][3], smb + SQ * 2 + qOff + ks * 32);

    float mrow[2] = {-1e30f, -1e30f};
    float lrow[2] = {0.f, 0.f};
    float accO[8][4];
    #pragma unroll
    for (int ni = 0; ni < 8; ni++)
        #pragma unroll
        for (int r = 0; r < 4; r++) accO[ni][r] = 0.f;

    for (int kt = 0; kt < SEQ / 128; kt++) {
        __syncthreads();   // all warps done reading the buffer about to be refilled
        if (kt + 1 < SEQ / 128) STAGE_KV(kt + 1, (kt + 1) & 1);
        asm volatile("cp.async.commit_group;" ::: "memory");
        asm volatile("cp.async.wait_group 1;" ::: "memory");
        __syncthreads();   // kt's K/V visible

        const uint32_t kBase = smb + (SK0 + (kt & 1) * KT_HALFS) * 2;
        const uint32_t vBase = smb + (SV0 + (kt & 1) * KT_HALFS) * 2;

        // ---- S = Q @ K^T ----
        float accS[16][4];
        #pragma unroll
        for (int ni = 0; ni < 16; ni++)
            #pragma unroll
            for (int r = 0; r < 4; r++) accS[ni][r] = 0.f;

        #pragma unroll
        for (int ks = 0; ks < 4; ks++) {
            const uint32_t kb = ks * 32;
            #pragma unroll
            for (int gg = 0; gg < 4; gg++) {
                uint32_t b0[4], b1[4];
                ldm_x4(b0[0], b0[1], b0[2], b0[3], kBase + kOff[gg] + kb);
                ldm_x4(b1[0], b1[1], b1[2], b1[3], kBase + kOff[gg] + kb + 16);
                #pragma unroll
                for (int j = 0; j < 4; j++)
                    mma_f16(accS[4 * gg + j], qa[ks][0], qa[ks][1], qa[ks][2], qa[ks][3],
                            b0[j], b1[j]);
            }
        }

        // ---- streaming softmax ----
        float mx0 = -1e30f, mx1 = -1e30f;
        #pragma unroll
        for (int ni = 0; ni < 16; ni++) {
            #pragma unroll
            for (int r = 0; r < 4; r++) accS[ni][r] *= 0.125f;
            mx0 = fmaxf(mx0, fmaxf(accS[ni][0], accS[ni][1]));
            mx1 = fmaxf(mx1, fmaxf(accS[ni][2], accS[ni][3]));
        }
        mx0 = fmaxf(mx0, __shfl_xor_sync(0xffffffffu, mx0, 1));
        mx0 = fmaxf(mx0, __shfl_xor_sync(0xffffffffu, mx0, 2));
        mx1 = fmaxf(mx1, __shfl_xor_sync(0xffffffffu, mx1, 1));
        mx1 = fmaxf(mx1, __shfl_xor_sync(0xffffffffu, mx1, 2));

        const float mn0 = fmaxf(mrow[0], mx0);
        const float mn1 = fmaxf(mrow[1], mx1);
        const float corr0 = __expf(mrow[0] - mn0);
        const float corr1 = __expf(mrow[1] - mn1);
        mrow[0] = mn0; mrow[1] = mn1;

        uint32_t pa[8][4];
        float sum0 = 0.f, sum1 = 0.f;
        #pragma unroll
        for (int ni = 0; ni < 16; ni++) {
            float p0 = __expf(accS[ni][0] - mn0);
            float p1 = __expf(accS[ni][1] - mn0);
            float p2 = __expf(accS[ni][2] - mn1);
            float p3 = __expf(accS[ni][3] - mn1);
            sum0 += p0 + p1;
            sum1 += p2 + p3;
            const int ks = ni >> 1;
            if (ni & 1) { pa[ks][2] = packh2(p0, p1); pa[ks][3] = packh2(p2, p3); }
            else        { pa[ks][0] = packh2(p0, p1); pa[ks][1] = packh2(p2, p3); }
        }
        sum0 += __shfl_xor_sync(0xffffffffu, sum0, 1);
        sum0 += __shfl_xor_sync(0xffffffffu, sum0, 2);
        sum1 += __shfl_xor_sync(0xffffffffu, sum1, 1);
        sum1 += __shfl_xor_sync(0xffffffffu, sum1, 2);
        lrow[0] = lrow[0] * corr0 + sum0;
        lrow[1] = lrow[1] * corr1 + sum1;

        #pragma unroll
        for (int ni = 0; ni < 8; ni++) {
            accO[ni][0] *= corr0; accO[ni][1] *= corr0;
            accO[ni][2] *= corr1; accO[ni][3] *= corr1;
        }

        // ---- O += P @ V (V frags via ldmatrix.trans on [key][d] tile) ----
        #pragma unroll
        for (int ks = 0; ks < 8; ks++) {
            const uint32_t kb = (uint32_t)(ks * 16 * AQ) * 2;   // key offset in bytes
            #pragma unroll
            for (int gg = 0; gg < 4; gg++) {
                uint32_t r0, r1, r2, r3;
                ldm_x4t(r0, r1, r2, r3, vBase + vOff[gg] + kb);
                mma_f16(accO[2 * gg + 0], pa[ks][0], pa[ks][1], pa[ks][2], pa[ks][3], r0, r1);
                mma_f16(accO[2 * gg + 1], pa[ks][0], pa[ks][1], pa[ks][2], pa[ks][3], r2, r3);
            }
        }
    }
    #undef STAGE_KV

    const float inv0 = 1.0f / lrow[0];
    const float inv1 = 1.0f / lrow[1];
    const int r0 = qrow0 + wid * 16 + frow;
    #pragma unroll
    for (int ni = 0; ni < 8; ni++) {
        const int col = h * HD + ni * 8 + 2 * t4;
        *(__half2*)(ctx + (size_t)r0 * D_MODEL + col) =
            __floats2half2_rn(accO[ni][0] * inv0, accO[ni][1] * inv0);
        *(__half2*)(ctx + (size_t)(r0 + 8) * D_MODEL + col) =
            __floats2half2_rn(accO[ni][2] * inv1, accO[ni][3] * inv1);
    }
}

// =================================================================
extern "C" void kernel_launch(void* const* d_in, const int* in_sizes, int n_in,
                              void* d_out, int out_size)
{
    const float* x  = (const float*)d_in[0];
    const float* Wq = (const float*)d_in[1];
    const float* bq = (const float*)d_in[2];
    const float* Wk = (const float*)d_in[3];
    const float* bk = (const float*)d_in[4];
    const float* Wv = (const float*)d_in[5];
    const float* bv = (const float*)d_in[6];
    const float* Wo = (const float*)d_in[7];
    const float* bo = (const float*)d_in[8];
    float* out = (float*)d_out;

    __half *qh, *kh, *vh, *ch, *xh, *wt3, *wto;
    cudaGetSymbolAddress((void**)&qh,  g_qh);
    cudaGetSymbolAddress((void**)&kh,  g_kh);
    cudaGetSymbolAddress((void**)&vh,  g_vh);
    cudaGetSymbolAddress((void**)&ch,  g_ch);
    cudaGetSymbolAddress((void**)&xh,  g_xh);
    cudaGetSymbolAddress((void**)&wt3, g_wt3);
    cudaGetSymbolAddress((void**)&wto, g_wto);

    cudaFuncSetAttribute(attn_h_kernel,
                         cudaFuncAttributeMaxDynamicSharedMemorySize, ATTN_SMEM_BYTES);
    cudaFuncSetAttribute(gemm_h_kernel,
                         cudaFuncAttributeMaxDynamicSharedMemorySize, GEMM_SMEM);

    dim3 tb(32, 8);

    // 1: x -> fp16
    {
        int n4 = MTOT * D_MODEL / 4;
        to_half_kernel<<<(n4 + 255) / 256, 256>>>((const float4*)x, (uint2*)xh, n4);
    }
    // 2: fused QKV weight transpose
    transpose3_kernel<<<dim3(D_MODEL / 32, D_MODEL / 32, 3), tb>>>(Wq, Wk, Wv, wt3);
    // 3: Wo transpose
    transpose_half_kernel<<<dim3(D_MODEL / 32, D_MODEL / 32), tb>>>(Wo, wto, D_MODEL, D_MODEL);

    // 4: fused QKV projection  <-- ncu-profiled launch
    gemm_h_kernel<<<dim3(NQKV / 128, MTOT / 128), 256, GEMM_SMEM>>>(
        xh, wt3, bq, bk, bv, nullptr, qh, kh, vh, MTOT, NQKV, D_MODEL, 1);

    // 5: attention (V loaded via ldmatrix.trans, no vtrans kernel)
    attn_h_kernel<<<dim3(SEQ / 128, NHEADS, BATCH), 256, ATTN_SMEM_BYTES>>>(qh, kh, vh, ch);

    // 6: output projection (fp32 out)
    gemm_h_kernel<<<dim3(D_MODEL / 128, MTOT / 128), 256, GEMM_SMEM>>>(
        ch, wto, bo, nullptr, nullptr, out, nullptr, nullptr, nullptr,
        MTOT, D_MODEL, D_MODEL, 0);
}

// round 14
// speedup vs baseline: 1.8587x; 1.1456x over previous
#include <cuda_runtime.h>
#include <cuda_fp16.h>
#include <cstdint>

#define D_MODEL 2048
#define KV_DIM  512
#define NHEADS  32
#define NKVH    8
#define HD      64
#define SEQ     1024
#define BATCH   4
#define MTOT    (BATCH * SEQ)   // 4096
#define NQKV    (D_MODEL + 2 * KV_DIM)  // 3072

// ---------------- scratch (no cudaMalloc allowed) ----------------
__device__ __align__(256) __half g_qh[MTOT * D_MODEL];
__device__ __align__(256) __half g_kh[MTOT * KV_DIM];
__device__ __align__(256) __half g_vh[MTOT * KV_DIM];
__device__ __align__(256) __half g_ch[MTOT * D_MODEL];     // attention ctx (fp16)
__device__ __align__(256) __half g_xh[MTOT * D_MODEL];     // x in fp16
__device__ __align__(256) __half g_wt3[NQKV * D_MODEL];    // [Wq;Wk;Wv] transposed fp16
__device__ __align__(256) __half g_wto[D_MODEL * D_MODEL]; // Wo transposed fp16

// ================= helpers =================
__device__ __forceinline__ uint32_t smem_u32(const void* p) {
    uint32_t a;
    asm("{ .reg .u64 t; cvta.to.shared.u64 t, %1; cvt.u32.u64 %0, t; }" : "=r"(a) : "l"(p));
    return a;
}
__device__ __forceinline__ void mma_f16(float c[4], uint32_t a0, uint32_t a1,
                                        uint32_t a2, uint32_t a3,
                                        uint32_t b0, uint32_t b1) {
    asm volatile(
        "mma.sync.aligned.m16n8k16.row.col.f32.f16.f16.f32 "
        "{%0,%1,%2,%3}, {%4,%5,%6,%7}, {%8,%9}, {%0,%1,%2,%3};"
        : "+f"(c[0]), "+f"(c[1]), "+f"(c[2]), "+f"(c[3])
        : "r"(a0), "r"(a1), "r"(a2), "r"(a3), "r"(b0), "r"(b1));
}
__device__ __forceinline__ void ldm_x4(uint32_t& r0, uint32_t& r1,
                                       uint32_t& r2, uint32_t& r3, uint32_t addr) {
    asm volatile("ldmatrix.sync.aligned.m8n8.x4.shared.b16 {%0,%1,%2,%3}, [%4];"
                 : "=r"(r0), "=r"(r1), "=r"(r2), "=r"(r3) : "r"(addr));
}
__device__ __forceinline__ void ldm_x4t(uint32_t& r0, uint32_t& r1,
                                        uint32_t& r2, uint32_t& r3, uint32_t addr) {
    asm volatile("ldmatrix.sync.aligned.m8n8.x4.trans.shared.b16 {%0,%1,%2,%3}, [%4];"
                 : "=r"(r0), "=r"(r1), "=r"(r2), "=r"(r3) : "r"(addr));
}
__device__ __forceinline__ uint32_t packh2(float a, float b) {
    __half2 h = __floats2half2_rn(a, b);
    return *(uint32_t*)&h;
}

// ================= prep kernels =================
__global__ void to_half_kernel(const float4* __restrict__ in, uint2* __restrict__ out, int n4) {
    int i = blockIdx.x * blockDim.x + threadIdx.x;
    if (i < n4) {
        float4 v = in[i];
        __half2 h0 = __floats2half2_rn(v.x, v.y);
        __half2 h1 = __floats2half2_rn(v.z, v.w);
        out[i] = make_uint2(*(uint32_t*)&h0, *(uint32_t*)&h1);
    }
}

// Fused Wq/Wk/Wv transpose: W [2048, N] fp32 -> wt3 region [N, 2048] fp16
__global__ void transpose3_kernel(const float* __restrict__ Wq, const float* __restrict__ Wk,
                                  const float* __restrict__ Wv, __half* __restrict__ wt3) {
    __shared__ float t[32][33];
    const int z = blockIdx.z;
    const float* W;
    __half* dst;
    int N;
    if (z == 0)      { W = Wq; N = D_MODEL; dst = wt3; }
    else if (z == 1) { W = Wk; N = KV_DIM;  dst = wt3 + (size_t)D_MODEL * D_MODEL; }
    else             { W = Wv; N = KV_DIM;  dst = wt3 + (size_t)(D_MODEL + KV_DIM) * D_MODEL; }
    const int n0 = blockIdx.x * 32;
    if (n0 >= N) return;
    const int k0 = blockIdx.y * 32;
    const int tx = threadIdx.x, ty = threadIdx.y;  // 32 x 8
    #pragma unroll
    for (int i = 0; i < 32; i += 8)
        t[ty + i][tx] = W[(size_t)(k0 + ty + i) * N + n0 + tx];
    __syncthreads();
    #pragma unroll
    for (int i = 0; i < 32; i += 8)
        dst[(size_t)(n0 + ty + i) * D_MODEL + k0 + tx] = __float2half_rn(t[tx][ty + i]);
}

// W [K, N] fp32 row-major -> Wt [N, K] fp16 row-major
__global__ void transpose_half_kernel(const float* __restrict__ W, __half* __restrict__ Wt,
                                      int K, int N) {
    __shared__ float t[32][33];
    const int n0 = blockIdx.x * 32, k0 = blockIdx.y * 32;
    const int tx = threadIdx.x, ty = threadIdx.y;  // 32 x 8
    #pragma unroll
    for (int i = 0; i < 32; i += 8)
        t[ty + i][tx] = W[(size_t)(k0 + ty + i) * N + n0 + tx];
    __syncthreads();
    #pragma unroll
    for (int i = 0; i < 32; i += 8)
        Wt[(size_t)(n0 + ty + i) * K + k0 + tx] = __float2half_rn(t[tx][ty + i]);
}

// ============ fp16 warp-MMA GEMM: 512 threads, 32x32 warp tiles ============
// 128x128 CTA tile, BK=64 halfs, 16 warps (4x4 -> 32x32 each), GS=3,
// pitch 72 halfs. 2 CTAs/SM (221 KB smem, 64 regs/thread).
#define GS   3
#define GPH  72
#define GA_STAGE (128 * GPH)            // halfs
#define GSTAGE_H (2 * 128 * GPH)
#define GEMM_SMEM (GS * GSTAGE_H * 2)   // 110592 B

__global__ __launch_bounds__(512, 2) void gemm_h_kernel(
    const __half* __restrict__ A, const __half* __restrict__ Bt,
    const float* __restrict__ bias0, const float* __restrict__ bias1,
    const float* __restrict__ bias2,
    float* __restrict__ outF,
    __half* __restrict__ outQ, __half* __restrict__ outK, __half* __restrict__ outV,
    int M, int N, int K, int mode)
{
    extern __shared__ __align__(16) __half hsm[];

    const int tid  = threadIdx.x;
    const int wid  = tid >> 5;
    const int lane = tid & 31;
    const int m0 = blockIdx.y * 128;
    const int n0 = blockIdx.x * 128;
    const int wm = wid & 3;    // 4 row-groups of 32
    const int wn = wid >> 2;   // 4 col-groups of 32
    const int frow = lane >> 2;
    const int t4   = lane & 3;

    // staging: 512 threads, each 4 x 16B; threads <256 -> A, >=256 -> B
    const bool isA = tid < 256;
    const int  t8  = tid & 255;
    const int  row = t8 >> 1;
    const int  off8 = (t8 & 1) * 4;    // sixteen-byte unit offset (0 or 4)
    const __half* gsrc = (isA ? (A + (size_t)(m0 + row) * K)
                              : (Bt + (size_t)(n0 + row) * K)) + off8 * 8;
    const uint32_t smem_base = smem_u32(hsm);
    const uint32_t sdst_row = smem_base + ((isA ? 0 : GA_STAGE) + row * GPH + off8 * 8) * 2;

    // ldmatrix lane offsets (bytes, relative to stage base)
    uint32_t aOff[2];
    #pragma unroll
    for (int mi = 0; mi < 2; mi++)
        aOff[mi] = ((wm * 32 + mi * 16 + (lane & 15)) * GPH + (lane >> 4) * 8) * 2;
    const uint32_t bOff = ((wn * 32 + (lane >> 3) * 8 + (lane & 7)) * GPH) * 2;

    const int nChunks = K / 64;

    #define GISSUE(ch, st) do {                                                \
        uint32_t _d = sdst_row + (st) * (GSTAGE_H * 2);                        \
        const __half* _g = gsrc + (ch) * 64;                                   \
        _Pragma("unroll")                                                      \
        for (int _c = 0; _c < 4; _c++)                                         \
            asm volatile("cp.async.cg.shared.global [%0], [%1], 16;"           \
                         :: "r"(_d + _c * 16), "l"(_g + _c * 8) : "memory");   \
    } while (0)

    GISSUE(0, 0);
    asm volatile("cp.async.commit_group;" ::: "memory");
    GISSUE(1, 1);
    asm volatile("cp.async.commit_group;" ::: "memory");

    float acc[2][4][4];
    #pragma unroll
    for (int mi = 0; mi < 2; mi++)
        #pragma unroll
        for (int ni = 0; ni < 4; ni++)
            #pragma unroll
            for (int r = 0; r < 4; r++) acc[mi][ni][r] = 0.f;

    for (int ch = 0; ch < nChunks; ch++) {
        asm volatile("cp.async.wait_group 1;" ::: "memory");
        __syncthreads();
        if (ch + 2 < nChunks) GISSUE(ch + 2, (ch + 2) % GS);
        asm volatile("cp.async.commit_group;" ::: "memory");

        const uint32_t stA = smem_base + (ch % GS) * (GSTAGE_H * 2);
        const uint32_t stB = stA + GA_STAGE * 2;

        #pragma unroll
        for (int ks = 0; ks < 4; ks++) {
            const uint32_t kb = ks * 32;   // bytes
            uint32_t a[2][4], b0[4], b1[4];
            #pragma unroll
            for (int mi = 0; mi < 2; mi++)
                ldm_x4(a[mi][0], a[mi][1], a[mi][2], a[mi][3], stA + aOff[mi] + kb);
            ldm_x4(b0[0], b0[1], b0[2], b0[3], stB + bOff + kb);
            ldm_x4(b1[0], b1[1], b1[2], b1[3], stB + bOff + kb + 16);
            #pragma unroll
            for (int mi = 0; mi < 2; mi++)
                #pragma unroll
                for (int ni = 0; ni < 4; ni++)
                    mma_f16(acc[mi][ni], a[mi][0], a[mi][1], a[mi][2], a[mi][3],
                            b0[ni], b1[ni]);
        }
    }
    #undef GISSUE

    // ---- epilogue ----
    const float* bias = bias0;
    __half* dstH = outQ;
    int colbase = n0, stride = N;
    if (mode == 1) {
        if (n0 < D_MODEL)               { dstH = outQ; bias = bias0; colbase = n0;              stride = D_MODEL; }
        else if (n0 < D_MODEL + KV_DIM) { dstH = outK; bias = bias1; colbase = n0 - D_MODEL;    stride = KV_DIM; }
        else                            { dstH = outV; bias = bias2; colbase = n0 - D_MODEL - KV_DIM; stride = KV_DIM; }
    }

    #pragma unroll
    for (int mi = 0; mi < 2; mi++) {
        const int r0 = m0 + wm * 32 + mi * 16 + frow;
        #pragma unroll
        for (int ni = 0; ni < 4; ni++) {
            const int col = colbase + wn * 32 + ni * 8 + 2 * t4;
            const float b0 = bias[col], b1 = bias[col + 1];
            const float v00 = acc[mi][ni][0] + b0, v01 = acc[mi][ni][1] + b1;
            const float v10 = acc[mi][ni][2] + b0, v11 = acc[mi][ni][3] + b1;
            if (mode == 1) {
                *(__half2*)(dstH + (size_t)r0 * stride + col) = __floats2half2_rn(v00, v01);
                *(__half2*)(dstH + (size_t)(r0 + 8) * stride + col) = __floats2half2_rn(v10, v11);
            } else {
                *(float2*)(outF + (size_t)r0 * stride + col) = make_float2(v00, v01);
                *(float2*)(outF + (size_t)(r0 + 8) * stride + col) = make_float2(v10, v11);
            }
        }
    }
}

// =================================================================
// fp16 flash attention (unchanged from R12): ldmatrix (+trans V),
// double-buffered K/V, P in registers, Q frags hoisted.
// =================================================================
#define AQ 72
#define KT_HALFS (128 * AQ)
#define SQ 0
#define SK0 (SQ + 128 * AQ)
#define SV0 (SK0 + 2 * KT_HALFS)
#define ATTN_HALFS (SV0 + 2 * KT_HALFS)
#define ATTN_SMEM_BYTES (ATTN_HALFS * 2)   // 92160 B

__global__ __launch_bounds__(256) void attn_h_kernel(
    const __half* __restrict__ q, const __half* __restrict__ k,
    const __half* __restrict__ v, __half* __restrict__ ctx)
{
    extern __shared__ __align__(16) __half hsm[];

    const int tid  = threadIdx.x;
    const int wid  = tid >> 5;
    const int lane = tid & 31;
    const int frow = lane >> 2;
    const int t4   = lane & 3;
    const int qt = blockIdx.x;
    const int h  = blockIdx.y;
    const int b  = blockIdx.z;
    const int kvh = h >> 2;

    const int qrow0 = b * SEQ + qt * 128;
    const __half* qbase = q + (size_t)qrow0 * D_MODEL + h * HD;
    const __half* kbase = k + (size_t)b * SEQ * KV_DIM + kvh * HD;
    const __half* vbase = v + (size_t)b * SEQ * KV_DIM + kvh * HD;

    const uint32_t smb = smem_u32(hsm);
    const int srow = tid >> 1;
    const int sc   = (tid & 1) * 32;

    {
        const __half* g = qbase + (size_t)srow * D_MODEL + sc;
        uint32_t d = smb + (SQ + srow * AQ + sc) * 2;
        #pragma unroll
        for (int c = 0; c < 4; c++)
            asm volatile("cp.async.cg.shared.global [%0], [%1], 16;"
                         :: "r"(d + c * 16), "l"(g + c * 8) : "memory");
        asm volatile("cp.async.commit_group;" ::: "memory");
    }

    #define STAGE_KV(kt, buf) do {                                             \
        const __half* gk = kbase + (size_t)((kt) * 128 + srow) * KV_DIM + sc;  \
        uint32_t dk = smb + (SK0 + (buf) * KT_HALFS + srow * AQ + sc) * 2;     \
        _Pragma("unroll")                                                      \
        for (int c = 0; c < 4; c++)                                            \
            asm volatile("cp.async.cg.shared.global [%0], [%1], 16;"           \
                         :: "r"(dk + c * 16), "l"(gk + c * 8) : "memory");     \
        const __half* gv = vbase + (size_t)((kt) * 128 + srow) * KV_DIM + sc;  \
        uint32_t dv = smb + (SV0 + (buf) * KT_HALFS + srow * AQ + sc) * 2;     \
        _Pragma("unroll")                                                      \
        for (int c = 0; c < 4; c++)                                            \
            asm volatile("cp.async.cg.shared.global [%0], [%1], 16;"           \
                         :: "r"(dv + c * 16), "l"(gv + c * 8) : "memory");     \
    } while (0)

    STAGE_KV(0, 0);
    asm volatile("cp.async.commit_group;" ::: "memory");

    const uint32_t qOff = ((wid * 16 + (lane & 15)) * AQ + (lane >> 4) * 8) * 2;
    uint32_t kOff[4];
    #pragma unroll
    for (int gg = 0; gg < 4; gg++)
        kOff[gg] = (((4 * gg + (lane >> 3)) * 8 + (lane & 7)) * AQ) * 2;
    uint32_t vOff[4];
    #pragma unroll
    for (int gg = 0; gg < 4; gg++) {
        const int vr = (lane & 7) + 8 * ((lane >> 3) & 1);
        const int vcd = (2 * gg + (lane >> 4)) * 8;
        vOff[gg] = (vr * AQ + vcd) * 2;
    }

    asm volatile("cp.async.wait_group 1;" ::: "memory");
    __syncthreads();
    uint32_t qa[4][4];
    #pragma unroll
    for (int ks = 0; ks < 4; ks++)
        ldm_x4(qa[ks][0], qa[ks][1], qa[ks][2], qa[ks][3], smb + SQ * 2 + qOff + ks * 32);

    float mrow[2] = {-1e30f, -1e30f};
    float lrow[2] = {0.f, 0.f};
    float accO[8][4];
    #pragma unroll
    for (int ni = 0; ni < 8; ni++)
        #pragma unroll
        for (int r = 0; r < 4; r++) accO[ni][r] = 0.f;

    for (int kt = 0; kt < SEQ / 128; kt++) {
        __syncthreads();
        if (kt + 1 < SEQ / 128) STAGE_KV(kt + 1, (kt + 1) & 1);
        asm volatile("cp.async.commit_group;" ::: "memory");
        asm volatile("cp.async.wait_group 1;" ::: "memory");
        __syncthreads();

        const uint32_t kBase = smb + (SK0 + (kt & 1) * KT_HALFS) * 2;
        const uint32_t vBase = smb + (SV0 + (kt & 1) * KT_HALFS) * 2;

        float accS[16][4];
        #pragma unroll
        for (int ni = 0; ni < 16; ni++)
            #pragma unroll
            for (int r = 0; r < 4; r++) accS[ni][r] = 0.f;

        #pragma unroll
        for (int ks = 0; ks < 4; ks++) {
            const uint32_t kb = ks * 32;
            #pragma unroll
            for (int gg = 0; gg < 4; gg++) {
                uint32_t b0[4], b1[4];
                ldm_x4(b0[0], b0[1], b0[2], b0[3], kBase + kOff[gg] + kb);
                ldm_x4(b1[0], b1[1], b1[2], b1[3], kBase + kOff[gg] + kb + 16);
                #pragma unroll
                for (int j = 0; j < 4; j++)
                    mma_f16(accS[4 * gg + j], qa[ks][0], qa[ks][1], qa[ks][2], qa[ks][3],
                            b0[j], b1[j]);
            }
        }

        float mx0 = -1e30f, mx1 = -1e30f;
        #pragma unroll
        for (int ni = 0; ni < 16; ni++) {
            #pragma unroll
            for (int r = 0; r < 4; r++) accS[ni][r] *= 0.125f;
            mx0 = fmaxf(mx0, fmaxf(accS[ni][0], accS[ni][1]));
            mx1 = fmaxf(mx1, fmaxf(accS[ni][2], accS[ni][3]));
        }
        mx0 = fmaxf(mx0, __shfl_xor_sync(0xffffffffu, mx0, 1));
        mx0 = fmaxf(mx0, __shfl_xor_sync(0xffffffffu, mx0, 2));
        mx1 = fmaxf(mx1, __shfl_xor_sync(0xffffffffu, mx1, 1));
        mx1 = fmaxf(mx1, __shfl_xor_sync(0xffffffffu, mx1, 2));

        const float mn0 = fmaxf(mrow[0], mx0);
        const float mn1 = fmaxf(mrow[1], mx1);
        const float corr0 = __expf(mrow[0] - mn0);
        const float corr1 = __expf(mrow[1] - mn1);
        mrow[0] = mn0; mrow[1] = mn1;

        uint32_t pa[8][4];
        float sum0 = 0.f, sum1 = 0.f;
        #pragma unroll
        for (int ni = 0; ni < 16; ni++) {
            float p0 = __expf(accS[ni][0] - mn0);
            float p1 = __expf(accS[ni][1] - mn0);
            float p2 = __expf(accS[ni][2] - mn1);
            float p3 = __expf(accS[ni][3] - mn1);
            sum0 += p0 + p1;
            sum1 += p2 + p3;
            const int ks = ni >> 1;
            if (ni & 1) { pa[ks][2] = packh2(p0, p1); pa[ks][3] = packh2(p2, p3); }
            else        { pa[ks][0] = packh2(p0, p1); pa[ks][1] = packh2(p2, p3); }
        }
        sum0 += __shfl_xor_sync(0xffffffffu, sum0, 1);
        sum0 += __shfl_xor_sync(0xffffffffu, sum0, 2);
        sum1 += __shfl_xor_sync(0xffffffffu, sum1, 1);
        sum1 += __shfl_xor_sync(0xffffffffu, sum1, 2);
        lrow[0] = lrow[0] * corr0 + sum0;
        lrow[1] = lrow[1] * corr1 + sum1;

        #pragma unroll
        for (int ni = 0; ni < 8; ni++) {
            accO[ni][0] *= corr0; accO[ni][1] *= corr0;
            accO[ni][2] *= corr1; accO[ni][3] *= corr1;
        }

        #pragma unroll
        for (int ks = 0; ks < 8; ks++) {
            const uint32_t kb = (uint32_t)(ks * 16 * AQ) * 2;
            #pragma unroll
            for (int gg = 0; gg < 4; gg++) {
                uint32_t r0, r1, r2, r3;
                ldm_x4t(r0, r1, r2, r3, vBase + vOff[gg] + kb);
                mma_f16(accO[2 * gg + 0], pa[ks][0], pa[ks][1], pa[ks][2], pa[ks][3], r0, r1);
                mma_f16(accO[2 * gg + 1], pa[ks][0], pa[ks][1], pa[ks][2], pa[ks][3], r2, r3);
            }
        }
    }
    #undef STAGE_KV

    const float inv0 = 1.0f / lrow[0];
    const float inv1 = 1.0f / lrow[1];
    const int r0 = qrow0 + wid * 16 + frow;
    #pragma unroll
    for (int ni = 0; ni < 8; ni++) {
        const int col = h * HD + ni * 8 + 2 * t4;
        *(__half2*)(ctx + (size_t)r0 * D_MODEL + col) =
            __floats2half2_rn(accO[ni][0] * inv0, accO[ni][1] * inv0);
        *(__half2*)(ctx + (size_t)(r0 + 8) * D_MODEL + col) =
            __floats2half2_rn(accO[ni][2] * inv1, accO[ni][3] * inv1);
    }
}

// =================================================================
extern "C" void kernel_launch(void* const* d_in, const int* in_sizes, int n_in,
                              void* d_out, int out_size)
{
    const float* x  = (const float*)d_in[0];
    const float* Wq = (const float*)d_in[1];
    const float* bq = (const float*)d_in[2];
    const float* Wk = (const float*)d_in[3];
    const float* bk = (const float*)d_in[4];
    const float* Wv = (const float*)d_in[5];
    const float* bv = (const float*)d_in[6];
    const float* Wo = (const float*)d_in[7];
    const float* bo = (const float*)d_in[8];
    float* out = (float*)d_out;

    __half *qh, *kh, *vh, *ch, *xh, *wt3, *wto;
    cudaGetSymbolAddress((void**)&qh,  g_qh);
    cudaGetSymbolAddress((void**)&kh,  g_kh);
    cudaGetSymbolAddress((void**)&vh,  g_vh);
    cudaGetSymbolAddress((void**)&ch,  g_ch);
    cudaGetSymbolAddress((void**)&xh,  g_xh);
    cudaGetSymbolAddress((void**)&wt3, g_wt3);
    cudaGetSymbolAddress((void**)&wto, g_wto);

    cudaFuncSetAttribute(attn_h_kernel,
                         cudaFuncAttributeMaxDynamicSharedMemorySize, ATTN_SMEM_BYTES);
    cudaFuncSetAttribute(gemm_h_kernel,
                         cudaFuncAttributeMaxDynamicSharedMemorySize, GEMM_SMEM);

    dim3 tb(32, 8);

    // 1: x -> fp16
    {
        int n4 = MTOT * D_MODEL / 4;
        to_half_kernel<<<(n4 + 255) / 256, 256>>>((const float4*)x, (uint2*)xh, n4);
    }
    // 2: fused QKV weight transpose
    transpose3_kernel<<<dim3(D_MODEL / 32, D_MODEL / 32, 3), tb>>>(Wq, Wk, Wv, wt3);
    // 3: Wo transpose
    transpose_half_kernel<<<dim3(D_MODEL / 32, D_MODEL / 32), tb>>>(Wo, wto, D_MODEL, D_MODEL);

    // 4: fused QKV projection  <-- ncu-profiled launch
    gemm_h_kernel<<<dim3(NQKV / 128, MTOT / 128), 512, GEMM_SMEM>>>(
        xh, wt3, bq, bk, bv, nullptr, qh, kh, vh, MTOT, NQKV, D_MODEL, 1);

    // 5: attention
    attn_h_kernel<<<dim3(SEQ / 128, NHEADS, BATCH), 256, ATTN_SMEM_BYTES>>>(qh, kh, vh, ch);

    // 6: output projection (fp32 out)
    gemm_h_kernel<<<dim3(D_MODEL / 128, MTOT / 128), 512, GEMM_SMEM>>>(
        ch, wto, bo, nullptr, nullptr, out, nullptr, nullptr, nullptr,
        MTOT, D_MODEL, D_MODEL, 0);
}

// round 15
// speedup vs baseline: 1.8911x; 1.0174x over previous
#include <cuda_runtime.h>
#include <cuda_fp16.h>
#include <cstdint>

#define D_MODEL 2048
#define KV_DIM  512
#define NHEADS  32
#define NKVH    8
#define HD      64
#define SEQ     1024
#define BATCH   4
#define MTOT    (BATCH * SEQ)   // 4096
#define NQKV    (D_MODEL + 2 * KV_DIM)  // 3072

// ---------------- scratch (no cudaMalloc allowed) ----------------
__device__ __align__(256) __half g_qh[MTOT * D_MODEL];
__device__ __align__(256) __half g_kh[MTOT * KV_DIM];
__device__ __align__(256) __half g_vh[MTOT * KV_DIM];
__device__ __align__(256) __half g_ch[MTOT * D_MODEL];     // attention ctx (fp16)
__device__ __align__(256) __half g_xh[MTOT * D_MODEL];     // x in fp16
__device__ __align__(256) __half g_wt3[NQKV * D_MODEL];    // [Wq;Wk;Wv] transposed fp16
__device__ __align__(256) __half g_wto[D_MODEL * D_MODEL]; // Wo transposed fp16

// ================= helpers =================
__device__ __forceinline__ uint32_t smem_u32(const void* p) {
    uint32_t a;
    asm("{ .reg .u64 t; cvta.to.shared.u64 t, %1; cvt.u32.u64 %0, t; }" : "=r"(a) : "l"(p));
    return a;
}
__device__ __forceinline__ void mma_f16(float c[4], uint32_t a0, uint32_t a1,
                                        uint32_t a2, uint32_t a3,
                                        uint32_t b0, uint32_t b1) {
    asm volatile(
        "mma.sync.aligned.m16n8k16.row.col.f32.f16.f16.f32 "
        "{%0,%1,%2,%3}, {%4,%5,%6,%7}, {%8,%9}, {%0,%1,%2,%3};"
        : "+f"(c[0]), "+f"(c[1]), "+f"(c[2]), "+f"(c[3])
        : "r"(a0), "r"(a1), "r"(a2), "r"(a3), "r"(b0), "r"(b1));
}
__device__ __forceinline__ void ldm_x4(uint32_t& r0, uint32_t& r1,
                                       uint32_t& r2, uint32_t& r3, uint32_t addr) {
    asm volatile("ldmatrix.sync.aligned.m8n8.x4.shared.b16 {%0,%1,%2,%3}, [%4];"
                 : "=r"(r0), "=r"(r1), "=r"(r2), "=r"(r3) : "r"(addr));
}
__device__ __forceinline__ void ldm_x4t(uint32_t& r0, uint32_t& r1,
                                        uint32_t& r2, uint32_t& r3, uint32_t addr) {
    asm volatile("ldmatrix.sync.aligned.m8n8.x4.trans.shared.b16 {%0,%1,%2,%3}, [%4];"
                 : "=r"(r0), "=r"(r1), "=r"(r2), "=r"(r3) : "r"(addr));
}
__device__ __forceinline__ uint32_t packh2(float a, float b) {
    __half2 h = __floats2half2_rn(a, b);
    return *(uint32_t*)&h;
}

// ================= prep kernels =================
__global__ void to_half_kernel(const float4* __restrict__ in, uint2* __restrict__ out, int n4) {
    int i = blockIdx.x * blockDim.x + threadIdx.x;
    if (i < n4) {
        float4 v = in[i];
        __half2 h0 = __floats2half2_rn(v.x, v.y);
        __half2 h1 = __floats2half2_rn(v.z, v.w);
        out[i] = make_uint2(*(uint32_t*)&h0, *(uint32_t*)&h1);
    }
}

// Fused Wq/Wk/Wv transpose: W [2048, N] fp32 -> wt3 region [N, 2048] fp16
__global__ void transpose3_kernel(const float* __restrict__ Wq, const float* __restrict__ Wk,
                                  const float* __restrict__ Wv, __half* __restrict__ wt3) {
    __shared__ float t[32][33];
    const int z = blockIdx.z;
    const float* W;
    __half* dst;
    int N;
    if (z == 0)      { W = Wq; N = D_MODEL; dst = wt3; }
    else if (z == 1) { W = Wk; N = KV_DIM;  dst = wt3 + (size_t)D_MODEL * D_MODEL; }
    else             { W = Wv; N = KV_DIM;  dst = wt3 + (size_t)(D_MODEL + KV_DIM) * D_MODEL; }
    const int n0 = blockIdx.x * 32;
    if (n0 >= N) return;
    const int k0 = blockIdx.y * 32;
    const int tx = threadIdx.x, ty = threadIdx.y;  // 32 x 8
    #pragma unroll
    for (int i = 0; i < 32; i += 8)
        t[ty + i][tx] = W[(size_t)(k0 + ty + i) * N + n0 + tx];
    __syncthreads();
    #pragma unroll
    for (int i = 0; i < 32; i += 8)
        dst[(size_t)(n0 + ty + i) * D_MODEL + k0 + tx] = __float2half_rn(t[tx][ty + i]);
}

// W [K, N] fp32 row-major -> Wt [N, K] fp16 row-major
__global__ void transpose_half_kernel(const float* __restrict__ W, __half* __restrict__ Wt,
                                      int K, int N) {
    __shared__ float t[32][33];
    const int n0 = blockIdx.x * 32, k0 = blockIdx.y * 32;
    const int tx = threadIdx.x, ty = threadIdx.y;  // 32 x 8
    #pragma unroll
    for (int i = 0; i < 32; i += 8)
        t[ty + i][tx] = W[(size_t)(k0 + ty + i) * N + n0 + tx];
    __syncthreads();
    #pragma unroll
    for (int i = 0; i < 32; i += 8)
        Wt[(size_t)(n0 + ty + i) * K + k0 + tx] = __float2half_rn(t[tx][ty + i]);
}

// ============ fp16 warp-MMA GEMM: 512 threads, 32x32 warp tiles ============
// (unchanged from R14: 2 CTA/SM, occ 46.6%)
#define GS   3
#define GPH  72
#define GA_STAGE (128 * GPH)
#define GSTAGE_H (2 * 128 * GPH)
#define GEMM_SMEM (GS * GSTAGE_H * 2)   // 110592 B

__global__ __launch_bounds__(512, 2) void gemm_h_kernel(
    const __half* __restrict__ A, const __half* __restrict__ Bt,
    const float* __restrict__ bias0, const float* __restrict__ bias1,
    const float* __restrict__ bias2,
    float* __restrict__ outF,
    __half* __restrict__ outQ, __half* __restrict__ outK, __half* __restrict__ outV,
    int M, int N, int K, int mode)
{
    extern __shared__ __align__(16) __half hsm[];

    const int tid  = threadIdx.x;
    const int wid  = tid >> 5;
    const int lane = tid & 31;
    const int m0 = blockIdx.y * 128;
    const int n0 = blockIdx.x * 128;
    const int wm = wid & 3;
    const int wn = wid >> 2;
    const int frow = lane >> 2;
    const int t4   = lane & 3;

    const bool isA = tid < 256;
    const int  t8  = tid & 255;
    const int  row = t8 >> 1;
    const int  off8 = (t8 & 1) * 4;
    const __half* gsrc = (isA ? (A + (size_t)(m0 + row) * K)
                              : (Bt + (size_t)(n0 + row) * K)) + off8 * 8;
    const uint32_t smem_base = smem_u32(hsm);
    const uint32_t sdst_row = smem_base + ((isA ? 0 : GA_STAGE) + row * GPH + off8 * 8) * 2;

    uint32_t aOff[2];
    #pragma unroll
    for (int mi = 0; mi < 2; mi++)
        aOff[mi] = ((wm * 32 + mi * 16 + (lane & 15)) * GPH + (lane >> 4) * 8) * 2;
    const uint32_t bOff = ((wn * 32 + (lane >> 3) * 8 + (lane & 7)) * GPH) * 2;

    const int nChunks = K / 64;

    #define GISSUE(ch, st) do {                                                \
        uint32_t _d = sdst_row + (st) * (GSTAGE_H * 2);                        \
        const __half* _g = gsrc + (ch) * 64;                                   \
        _Pragma("unroll")                                                      \
        for (int _c = 0; _c < 4; _c++)                                         \
            asm volatile("cp.async.cg.shared.global [%0], [%1], 16;"           \
                         :: "r"(_d + _c * 16), "l"(_g + _c * 8) : "memory");   \
    } while (0)

    GISSUE(0, 0);
    asm volatile("cp.async.commit_group;" ::: "memory");
    GISSUE(1, 1);
    asm volatile("cp.async.commit_group;" ::: "memory");

    float acc[2][4][4];
    #pragma unroll
    for (int mi = 0; mi < 2; mi++)
        #pragma unroll
        for (int ni = 0; ni < 4; ni++)
            #pragma unroll
            for (int r = 0; r < 4; r++) acc[mi][ni][r] = 0.f;

    for (int ch = 0; ch < nChunks; ch++) {
        asm volatile("cp.async.wait_group 1;" ::: "memory");
        __syncthreads();
        if (ch + 2 < nChunks) GISSUE(ch + 2, (ch + 2) % GS);
        asm volatile("cp.async.commit_group;" ::: "memory");

        const uint32_t stA = smem_base + (ch % GS) * (GSTAGE_H * 2);
        const uint32_t stB = stA + GA_STAGE * 2;

        #pragma unroll
        for (int ks = 0; ks < 4; ks++) {
            const uint32_t kb = ks * 32;
            uint32_t a[2][4], b0[4], b1[4];
            #pragma unroll
            for (int mi = 0; mi < 2; mi++)
                ldm_x4(a[mi][0], a[mi][1], a[mi][2], a[mi][3], stA + aOff[mi] + kb);
            ldm_x4(b0[0], b0[1], b0[2], b0[3], stB + bOff + kb);
            ldm_x4(b1[0], b1[1], b1[2], b1[3], stB + bOff + kb + 16);
            #pragma unroll
            for (int mi = 0; mi < 2; mi++)
                #pragma unroll
                for (int ni = 0; ni < 4; ni++)
                    mma_f16(acc[mi][ni], a[mi][0], a[mi][1], a[mi][2], a[mi][3],
                            b0[ni], b1[ni]);
        }
    }
    #undef GISSUE

    const float* bias = bias0;
    __half* dstH = outQ;
    int colbase = n0, stride = N;
    if (mode == 1) {
        if (n0 < D_MODEL)               { dstH = outQ; bias = bias0; colbase = n0;              stride = D_MODEL; }
        else if (n0 < D_MODEL + KV_DIM) { dstH = outK; bias = bias1; colbase = n0 - D_MODEL;    stride = KV_DIM; }
        else                            { dstH = outV; bias = bias2; colbase = n0 - D_MODEL - KV_DIM; stride = KV_DIM; }
    }

    #pragma unroll
    for (int mi = 0; mi < 2; mi++) {
        const int r0 = m0 + wm * 32 + mi * 16 + frow;
        #pragma unroll
        for (int ni = 0; ni < 4; ni++) {
            const int col = colbase + wn * 32 + ni * 8 + 2 * t4;
            const float b0 = bias[col], b1 = bias[col + 1];
            const float v00 = acc[mi][ni][0] + b0, v01 = acc[mi][ni][1] + b1;
            const float v10 = acc[mi][ni][2] + b0, v11 = acc[mi][ni][3] + b1;
            if (mode == 1) {
                *(__half2*)(dstH + (size_t)r0 * stride + col) = __floats2half2_rn(v00, v01);
                *(__half2*)(dstH + (size_t)(r0 + 8) * stride + col) = __floats2half2_rn(v10, v11);
            } else {
                *(float2*)(outF + (size_t)r0 * stride + col) = make_float2(v00, v01);
                *(float2*)(outF + (size_t)(r0 + 8) * stride + col) = make_float2(v10, v11);
            }
        }
    }
}

// =================================================================
// fp16 flash attention v2: 64-key half-tiles (S -> softmax -> PV per
// half) to halve transient regs; __launch_bounds__(256,2) -> 2 CTA/SM.
// =================================================================
#define AQ 72
#define KT_HALFS (128 * AQ)
#define SQ 0
#define SK0 (SQ + 128 * AQ)
#define SV0 (SK0 + 2 * KT_HALFS)
#define ATTN_HALFS (SV0 + 2 * KT_HALFS)
#define ATTN_SMEM_BYTES (ATTN_HALFS * 2)   // 92160 B

__global__ __launch_bounds__(256, 2) void attn_h_kernel(
    const __half* __restrict__ q, const __half* __restrict__ k,
    const __half* __restrict__ v, __half* __restrict__ ctx)
{
    extern __shared__ __align__(16) __half hsm[];

    const int tid  = threadIdx.x;
    const int wid  = tid >> 5;
    const int lane = tid & 31;
    const int frow = lane >> 2;
    const int t4   = lane & 3;
    const int qt = blockIdx.x;
    const int h  = blockIdx.y;
    const int b  = blockIdx.z;
    const int kvh = h >> 2;

    const int qrow0 = b * SEQ + qt * 128;
    const __half* qbase = q + (size_t)qrow0 * D_MODEL + h * HD;
    const __half* kbase = k + (size_t)b * SEQ * KV_DIM + kvh * HD;
    const __half* vbase = v + (size_t)b * SEQ * KV_DIM + kvh * HD;

    const uint32_t smb = smem_u32(hsm);
    const int srow = tid >> 1;
    const int sc   = (tid & 1) * 32;

    {
        const __half* g = qbase + (size_t)srow * D_MODEL + sc;
        uint32_t d = smb + (SQ + srow * AQ + sc) * 2;
        #pragma unroll
        for (int c = 0; c < 4; c++)
            asm volatile("cp.async.cg.shared.global [%0], [%1], 16;"
                         :: "r"(d + c * 16), "l"(g + c * 8) : "memory");
        asm volatile("cp.async.commit_group;" ::: "memory");
    }

    #define STAGE_KV(kt, buf) do {                                             \
        const __half* gk = kbase + (size_t)((kt) * 128 + srow) * KV_DIM + sc;  \
        uint32_t dk = smb + (SK0 + (buf) * KT_HALFS + srow * AQ + sc) * 2;     \
        _Pragma("unroll")                                                      \
        for (int c = 0; c < 4; c++)                                            \
            asm volatile("cp.async.cg.shared.global [%0], [%1], 16;"           \
                         :: "r"(dk + c * 16), "l"(gk + c * 8) : "memory");     \
        const __half* gv = vbase + (size_t)((kt) * 128 + srow) * KV_DIM + sc;  \
        uint32_t dv = smb + (SV0 + (buf) * KT_HALFS + srow * AQ + sc) * 2;     \
        _Pragma("unroll")                                                      \
        for (int c = 0; c < 4; c++)                                            \
            asm volatile("cp.async.cg.shared.global [%0], [%1], 16;"           \
                         :: "r"(dv + c * 16), "l"(gv + c * 8) : "memory");     \
    } while (0)

    STAGE_KV(0, 0);
    asm volatile("cp.async.commit_group;" ::: "memory");

    const uint32_t qOff = ((wid * 16 + (lane & 15)) * AQ + (lane >> 4) * 8) * 2;
    uint32_t kOff[4];
    #pragma unroll
    for (int gg = 0; gg < 4; gg++)
        kOff[gg] = (((4 * gg + (lane >> 3)) * 8 + (lane & 7)) * AQ) * 2;
    uint32_t vOff[4];
    #pragma unroll
    for (int gg = 0; gg < 4; gg++) {
        const int vr = (lane & 7) + 8 * ((lane >> 3) & 1);
        const int vcd = (2 * gg + (lane >> 4)) * 8;
        vOff[gg] = (vr * AQ + vcd) * 2;
    }

    asm volatile("cp.async.wait_group 1;" ::: "memory");
    __syncthreads();
    uint32_t qa[4][4];
    #pragma unroll
    for (int ks = 0; ks < 4; ks++)
        ldm_x4(qa[ks][0], qa[ks][1], qa[ks][2], qa[ks][3], smb + SQ * 2 + qOff + ks * 32);

    float mrow[2] = {-1e30f, -1e30f};
    float lrow[2] = {0.f, 0.f};
    float accO[8][4];
    #pragma unroll
    for (int ni = 0; ni < 8; ni++)
        #pragma unroll
        for (int r = 0; r < 4; r++) accO[ni][r] = 0.f;

    for (int kt = 0; kt < SEQ / 128; kt++) {
        __syncthreads();
        if (kt + 1 < SEQ / 128) STAGE_KV(kt + 1, (kt + 1) & 1);
        asm volatile("cp.async.commit_group;" ::: "memory");
        asm volatile("cp.async.wait_group 1;" ::: "memory");
        __syncthreads();

        const uint32_t kBase = smb + (SK0 + (kt & 1) * KT_HALFS) * 2;
        const uint32_t vBase = smb + (SV0 + (kt & 1) * KT_HALFS) * 2;

        #pragma unroll
        for (int half = 0; half < 2; half++) {
            // ---- S for 64 keys ----
            float accS[8][4];
            #pragma unroll
            for (int ni = 0; ni < 8; ni++)
                #pragma unroll
                for (int r = 0; r < 4; r++) accS[ni][r] = 0.f;

            #pragma unroll
            for (int ks = 0; ks < 4; ks++) {
                const uint32_t kb = ks * 32;
                #pragma unroll
                for (int gg = 0; gg < 2; gg++) {
                    uint32_t b0[4], b1[4];
                    ldm_x4(b0[0], b0[1], b0[2], b0[3], kBase + kOff[2 * half + gg] + kb);
                    ldm_x4(b1[0], b1[1], b1[2], b1[3], kBase + kOff[2 * half + gg] + kb + 16);
                    #pragma unroll
                    for (int j = 0; j < 4; j++)
                        mma_f16(accS[4 * gg + j], qa[ks][0], qa[ks][1], qa[ks][2], qa[ks][3],
                                b0[j], b1[j]);
                }
            }

            // ---- softmax update over these 64 keys ----
            float mx0 = -1e30f, mx1 = -1e30f;
            #pragma unroll
            for (int ni = 0; ni < 8; ni++) {
                #pragma unroll
                for (int r = 0; r < 4; r++) accS[ni][r] *= 0.125f;
                mx0 = fmaxf(mx0, fmaxf(accS[ni][0], accS[ni][1]));
                mx1 = fmaxf(mx1, fmaxf(accS[ni][2], accS[ni][3]));
            }
            mx0 = fmaxf(mx0, __shfl_xor_sync(0xffffffffu, mx0, 1));
            mx0 = fmaxf(mx0, __shfl_xor_sync(0xffffffffu, mx0, 2));
            mx1 = fmaxf(mx1, __shfl_xor_sync(0xffffffffu, mx1, 1));
            mx1 = fmaxf(mx1, __shfl_xor_sync(0xffffffffu, mx1, 2));

            const float mn0 = fmaxf(mrow[0], mx0);
            const float mn1 = fmaxf(mrow[1], mx1);
            const float corr0 = __expf(mrow[0] - mn0);
            const float corr1 = __expf(mrow[1] - mn1);
            mrow[0] = mn0; mrow[1] = mn1;

            uint32_t pa[4][4];
            float sum0 = 0.f, sum1 = 0.f;
            #pragma unroll
            for (int ni = 0; ni < 8; ni++) {
                float p0 = __expf(accS[ni][0] - mn0);
                float p1 = __expf(accS[ni][1] - mn0);
                float p2 = __expf(accS[ni][2] - mn1);
                float p3 = __expf(accS[ni][3] - mn1);
                sum0 += p0 + p1;
                sum1 += p2 + p3;
                const int ks = ni >> 1;
                if (ni & 1) { pa[ks][2] = packh2(p0, p1); pa[ks][3] = packh2(p2, p3); }
                else        { pa[ks][0] = packh2(p0, p1); pa[ks][1] = packh2(p2, p3); }
            }
            sum0 += __shfl_xor_sync(0xffffffffu, sum0, 1);
            sum0 += __shfl_xor_sync(0xffffffffu, sum0, 2);
            sum1 += __shfl_xor_sync(0xffffffffu, sum1, 1);
            sum1 += __shfl_xor_sync(0xffffffffu, sum1, 2);
            lrow[0] = lrow[0] * corr0 + sum0;
            lrow[1] = lrow[1] * corr1 + sum1;

            #pragma unroll
            for (int ni = 0; ni < 8; ni++) {
                accO[ni][0] *= corr0; accO[ni][1] *= corr0;
                accO[ni][2] *= corr1; accO[ni][3] *= corr1;
            }

            // ---- O += P @ V over these 64 keys ----
            #pragma unroll
            for (int ks = 0; ks < 4; ks++) {
                const uint32_t kb = (uint32_t)((half * 64 + ks * 16) * AQ) * 2;
                #pragma unroll
                for (int gg = 0; gg < 4; gg++) {
                    uint32_t r0, r1, r2, r3;
                    ldm_x4t(r0, r1, r2, r3, vBase + vOff[gg] + kb);
                    mma_f16(accO[2 * gg + 0], pa[ks][0], pa[ks][1], pa[ks][2], pa[ks][3], r0, r1);
                    mma_f16(accO[2 * gg + 1], pa[ks][0], pa[ks][1], pa[ks][2], pa[ks][3], r2, r3);
                }
            }
        }
    }
    #undef STAGE_KV

    const float inv0 = 1.0f / lrow[0];
    const float inv1 = 1.0f / lrow[1];
    const int r0 = qrow0 + wid * 16 + frow;
    #pragma unroll
    for (int ni = 0; ni < 8; ni++) {
        const int col = h * HD + ni * 8 + 2 * t4;
        *(__half2*)(ctx + (size_t)r0 * D_MODEL + col) =
            __floats2half2_rn(accO[ni][0] * inv0, accO[ni][1] * inv0);
        *(__half2*)(ctx + (size_t)(r0 + 8) * D_MODEL + col) =
            __floats2half2_rn(accO[ni][2] * inv1, accO[ni][3] * inv1);
    }
}

// =================================================================
extern "C" void kernel_launch(void* const* d_in, const int* in_sizes, int n_in,
                              void* d_out, int out_size)
{
    const float* x  = (const float*)d_in[0];
    const float* Wq = (const float*)d_in[1];
    const float* bq = (const float*)d_in[2];
    const float* Wk = (const float*)d_in[3];
    const float* bk = (const float*)d_in[4];
    const float* Wv = (const float*)d_in[5];
    const float* bv = (const float*)d_in[6];
    const float* Wo = (const float*)d_in[7];
    const float* bo = (const float*)d_in[8];
    float* out = (float*)d_out;

    __half *qh, *kh, *vh, *ch, *xh, *wt3, *wto;
    cudaGetSymbolAddress((void**)&qh,  g_qh);
    cudaGetSymbolAddress((void**)&kh,  g_kh);
    cudaGetSymbolAddress((void**)&vh,  g_vh);
    cudaGetSymbolAddress((void**)&ch,  g_ch);
    cudaGetSymbolAddress((void**)&xh,  g_xh);
    cudaGetSymbolAddress((void**)&wt3, g_wt3);
    cudaGetSymbolAddress((void**)&wto, g_wto);

    cudaFuncSetAttribute(attn_h_kernel,
                         cudaFuncAttributeMaxDynamicSharedMemorySize, ATTN_SMEM_BYTES);
    cudaFuncSetAttribute(gemm_h_kernel,
                         cudaFuncAttributeMaxDynamicSharedMemorySize, GEMM_SMEM);

    dim3 tb(32, 8);

    // 1: x -> fp16
    {
        int n4 = MTOT * D_MODEL / 4;
        to_half_kernel<<<(n4 + 255) / 256, 256>>>((const float4*)x, (uint2*)xh, n4);
    }
    // 2: fused QKV weight transpose
    transpose3_kernel<<<dim3(D_MODEL / 32, D_MODEL / 32, 3), tb>>>(Wq, Wk, Wv, wt3);
    // 3: Wo transpose
    transpose_half_kernel<<<dim3(D_MODEL / 32, D_MODEL / 32), tb>>>(Wo, wto, D_MODEL, D_MODEL);

    // 4: fused QKV projection  <-- ncu-profiled launch
    gemm_h_kernel<<<dim3(NQKV / 128, MTOT / 128), 512, GEMM_SMEM>>>(
        xh, wt3, bq, bk, bv, nullptr, qh, kh, vh, MTOT, NQKV, D_MODEL, 1);

    // 5: attention
    attn_h_kernel<<<dim3(SEQ / 128, NHEADS, BATCH), 256, ATTN_SMEM_BYTES>>>(qh, kh, vh, ch);

    // 6: output projection (fp32 out)
    gemm_h_kernel<<<dim3(D_MODEL / 128, MTOT / 128), 512, GEMM_SMEM>>>(
        ch, wto, bo, nullptr, nullptr, out, nullptr, nullptr, nullptr,
        MTOT, D_MODEL, D_MODEL, 0);
}